// round 13
// baseline (speedup 1.0000x reference)
#include <cuda_runtime.h>
#include <cuda_bf16.h>
#include <cuda_fp16.h>
#include <cstdint>

// ---------------------------------------------------------------------------
// Shapes: B=2, C=256, Im 768x1280, strides {4,8,16,32}, N=1024 rois
// pool5 D = 12544 BIN-MAJOR (d = bin*256 + ch); fc1_w permuted to match.
// fc1: 12544->1024 relu; fc2: 1024->1024 relu; proj->20
// ---------------------------------------------------------------------------

#define NCH 256

#if defined(__CUDA_ARCH__) && defined(__CUDA_ARCH_FEAT_SM103_ALL)
#define HAS_TCGEN05 1
#else
#define HAS_TCGEN05 0
#endif

__device__ __half g_nhwc[41779200];
__device__ __nv_bfloat16 g_p5_hi[1024 * 12544];
__device__ __nv_bfloat16 g_p5_lo[1024 * 12544];
__device__ __nv_bfloat16 g_w1_hi[1024 * 12544];
__device__ __nv_bfloat16 g_w1_lo[1024 * 12544];
__device__ __nv_bfloat16 g_fc1_hi[1024 * 1024];
__device__ __nv_bfloat16 g_fc1_lo[1024 * 1024];
__device__ __nv_bfloat16 g_w2_hi[1024 * 1024];
__device__ __nv_bfloat16 g_w2_lo[1024 * 1024];
__device__ float g_part[4 * 1024 * 1024];    // split-K4 partials

__constant__ size_t c_lvl_off[4] = {0, 31457280, 39321600, 41287680};

// ============================ PTX helpers ==================================
__device__ __forceinline__ uint32_t smem_u32(const void* p) {
    uint32_t a;
    asm("{ .reg .u64 t; cvta.to.shared.u64 t, %1; cvt.u32.u64 %0, t; }" : "=r"(a) : "l"(p));
    return a;
}
__device__ __forceinline__ uint32_t elect_one() {
    uint32_t p;
    asm volatile("{\n\t.reg .pred p;\n\telect.sync _|p, 0xFFFFFFFF;\n\tselp.b32 %0, 1, 0, p;\n\t}" : "=r"(p));
    return p;
}
#define MBARRIER_INIT(addr, cnt) \
    asm volatile("mbarrier.init.shared.b64 [%0], %1;" :: "r"(addr), "r"(cnt) : "memory")
#define MBARRIER_WAIT_PARITY(addr, par) do {                                          \
    uint32_t _m = (addr); uint32_t _p = (par); uint32_t _d;                           \
    asm volatile("{\n\t.reg .pred p;\n\t"                                             \
        "mbarrier.try_wait.parity.acquire.cta.shared::cta.b64 p, [%1], %2;\n\t"       \
        "selp.b32 %0, 1, 0, p;\n\t}" : "=r"(_d) : "r"(_m), "r"(_p) : "memory");       \
    if (!_d) {                                                                        \
        asm volatile("{\n\t.reg .pred P1;\n\t"                                        \
            "WL_%=:\n\t"                                                              \
            "mbarrier.try_wait.parity.acquire.cta.shared::cta.b64 P1, [%0], %1, 0x989680;\n\t" \
            "@P1 bra.uni WD_%=;\n\tbra.uni WL_%=;\n\tWD_%=:\n\t}"                     \
            :: "r"(_m), "r"(_p) : "memory");                                          \
    } } while (0)
#define FENCE_PROXY_ASYNC() asm volatile("fence.proxy.async.shared::cta;" ::: "memory")
#define CP_COMMIT() asm volatile("cp.async.commit_group;" ::: "memory")
#define CP_WAIT_0() asm volatile("cp.async.wait_group 0;" ::: "memory")

#if HAS_TCGEN05
#define TCGEN05_ALLOC(sa, n) \
    asm volatile("tcgen05.alloc.cta_group::1.sync.aligned.shared::cta.b32 [%0], %1;" :: "r"(sa), "r"(n) : "memory")
#define TCGEN05_DEALLOC(t, n) \
    asm volatile("tcgen05.dealloc.cta_group::1.sync.aligned.b32 %0, %1;" :: "r"(t), "r"(n))
#define TCGEN05_RELINQ() \
    asm volatile("tcgen05.relinquish_alloc_permit.cta_group::1.sync.aligned;")
#define TCGEN05_COMMIT(mb) \
    asm volatile("tcgen05.commit.cta_group::1.mbarrier::arrive::one.shared::cluster.b64 [%0];" :: "r"(mb) : "memory")
#define TCGEN05_FENCE_AFTER()  asm volatile("tcgen05.fence::after_thread_sync;" ::: "memory")
#define TCGEN05_FENCE_BEFORE() asm volatile("tcgen05.fence::before_thread_sync;" ::: "memory")
#define TCGEN05_WAIT_LD() asm volatile("tcgen05.wait::ld.sync.aligned;" ::: "memory")

#define TCGEN05_LD_X32(r, ta)                                                          \
    asm volatile("tcgen05.ld.sync.aligned.32x32b.x32.b32 "                             \
        "{%0, %1, %2, %3, %4, %5, %6, %7, %8, %9, %10, %11, %12, %13, %14, %15, "      \
        " %16, %17, %18, %19, %20, %21, %22, %23, %24, %25, %26, %27, %28, %29, %30, %31}, [%32];" \
        : "=r"((r)[0]), "=r"((r)[1]), "=r"((r)[2]), "=r"((r)[3]),                      \
          "=r"((r)[4]), "=r"((r)[5]), "=r"((r)[6]), "=r"((r)[7]),                      \
          "=r"((r)[8]), "=r"((r)[9]), "=r"((r)[10]), "=r"((r)[11]),                    \
          "=r"((r)[12]), "=r"((r)[13]), "=r"((r)[14]), "=r"((r)[15]),                  \
          "=r"((r)[16]), "=r"((r)[17]), "=r"((r)[18]), "=r"((r)[19]),                  \
          "=r"((r)[20]), "=r"((r)[21]), "=r"((r)[22]), "=r"((r)[23]),                  \
          "=r"((r)[24]), "=r"((r)[25]), "=r"((r)[26]), "=r"((r)[27]),                  \
          "=r"((r)[28]), "=r"((r)[29]), "=r"((r)[30]), "=r"((r)[31])                   \
        : "r"(ta))

__device__ __forceinline__ void mma_f16_ss(uint32_t d, uint64_t a, uint64_t b,
                                           uint32_t idesc, bool en) {
    uint32_t e = en ? 1u : 0u;
    asm volatile(
        "{\n\t.reg .pred p;\n\tsetp.ne.u32 p, %4, 0;\n\t"
        "tcgen05.mma.cta_group::1.kind::f16 [%0], %1, %2, %3, {%5, %5, %5, %5}, p;\n\t}"
        :: "r"(d), "l"(a), "l"(b), "r"(idesc), "r"(e), "r"(0u) : "memory");
}
#endif  // HAS_TCGEN05

// SW128 K-major descriptor: layout=2, version=1, SBO=64, LBO=1
static constexpr uint64_t DESC_BASE_SW128 =
    (uint64_t(2) << 61) | (uint64_t(1) << 46) | (uint64_t(64) << 32) | (uint64_t(1) << 16);
#define MAKE_DESC(a) (DESC_BASE_SW128 | ((uint64_t)((a) >> 4) & 0x3FFF))

// idesc kind::f16: F32 accum, BF16 a/b, M=128, N=256
static constexpr uint32_t GEMM_IDESC =
    (1u << 4) | (1u << 7) | (1u << 10) | ((256u / 8u) << 17) | ((128u / 16u) << 24);

__device__ __forceinline__ void pack_hi_lo(float v0, float v1, uint32_t& h, uint32_t& l) {
    asm("cvt.rn.bf16x2.f32 %0, %1, %2;" : "=r"(h) : "f"(v1), "f"(v0));
    float l0 = v0 - __uint_as_float(h << 16);
    float l1 = v1 - __uint_as_float(h & 0xffff0000u);
    asm("cvt.rn.bf16x2.f32 %0, %1, %2;" : "=r"(l) : "f"(l1), "f"(l0));
}

// ---------------------------------------------------------------------------
// All-level NCHW fp32 -> NHWC fp16 transpose in ONE launch.
// ---------------------------------------------------------------------------
__global__ void nchw2nhwc_all_kernel(const float* __restrict__ fm0,
                                     const float* __restrict__ fm1,
                                     const float* __restrict__ fm2,
                                     const float* __restrict__ fm3) {
    __shared__ float tile[8][32][33];
    int bx = blockIdx.x;
    int lvl, bl;
    if      (bx < 240) { lvl = 0; bl = bx; }
    else if (bx < 300) { lvl = 1; bl = bx - 240; }
    else if (bx < 315) { lvl = 2; bl = bx - 300; }
    else               { lvl = 3; bl = bx - 315; }
    int HW = 61440 >> (2 * lvl);
    const float* in = (lvl == 0) ? fm0 : (lvl == 1) ? fm1 : (lvl == 2) ? fm2 : fm3;
    size_t off = c_lvl_off[lvl];

    int b = blockIdx.z;
    int c0 = blockIdx.y * 32;
    int t = threadIdx.x;
    int cr  = t >> 3;
    int f4  = t & 7;

    int hwbase = bl * 256;
    int nrep = (HW - hwbase + 31) >> 5;
    if (nrep > 8) nrep = 8;

    float4 v[8];
#pragma unroll
    for (int rep = 0; rep < 8; rep++)
        if (rep < nrep)
            v[rep] = *((const float4*)(in + ((size_t)b * NCH + c0 + cr) * HW + hwbase + rep * 32) + f4);

#pragma unroll
    for (int rep = 0; rep < 8; rep++)
        if (rep < nrep) {
            tile[rep][f4 * 4 + 0][cr] = v[rep].x;
            tile[rep][f4 * 4 + 1][cr] = v[rep].y;
            tile[rep][f4 * 4 + 2][cr] = v[rep].z;
            tile[rep][f4 * 4 + 3][cr] = v[rep].w;
        }
    __syncthreads();

#pragma unroll
    for (int rep = 0; rep < 8; rep++)
        if (rep < nrep) {
            half2 a = __floats2half2_rn(tile[rep][cr][f4 * 4 + 0], tile[rep][cr][f4 * 4 + 1]);
            half2 c = __floats2half2_rn(tile[rep][cr][f4 * 4 + 2], tile[rep][cr][f4 * 4 + 3]);
            uint2 o;
            o.x = *(uint32_t*)&a;
            o.y = *(uint32_t*)&c;
            *(uint2*)(g_nhwc + off + ((size_t)b * HW + hwbase + rep * 32 + cr) * NCH + c0 + f4 * 4) = o;
        }
}

// ---------------------------------------------------------------------------
// ROIAlign from fp16 NHWC: bin-major direct hi/lo uint4 output.
// ---------------------------------------------------------------------------
__device__ __forceinline__ void acc8(float* acc, uint4 v, float w) {
    half2* h = (half2*)&v;
#pragma unroll
    for (int e = 0; e < 4; e++) {
        float2 f = __half22float2(h[e]);
        acc[2 * e]     += w * f.x;
        acc[2 * e + 1] += w * f.y;
    }
}

__global__ __launch_bounds__(256) void roi_align_kernel(const float* __restrict__ rois) {
    __shared__ int   s_ix0[14], s_ix1[14], s_iy0[14], s_iy1[14];
    __shared__ float s_wx0[14], s_wx1[14], s_wy0[14], s_wy1[14];

    int n = blockIdx.x;
    int tid = threadIdx.x;
    int c8  = tid & 31;
    int grp = tid >> 5;

    const float* r = rois + (size_t)n * 5;
    int   b  = (int)r[0];
    float x1 = r[1], y1 = r[2], x2 = r[3], y2 = r[4];

    float w = x2 - x1, h = y2 - y1;
    float kf = floorf(4.0f + log2f(sqrtf(fmaxf(w * h, 1e-6f)) / 224.0f));
    kf = fminf(fmaxf(kf, 2.0f), 5.0f);
    int lvl = (int)kf - 2;

    float stride = (float)(4 << lvl);
    int H = 768 >> (lvl + 2);
    int W = 1280 >> (lvl + 2);
    const uint4* base4 = (const uint4*)(g_nhwc + c_lvl_off[lvl] + (size_t)b * H * W * NCH);

    if (tid < 28) {
        bool isx = tid < 14;
        int  s   = isx ? tid : tid - 14;
        float lo = isx ? x1 : y1;
        float hi = isx ? x2 : y2;
        int size = isx ? W : H;
        float a = lo / stride - 0.5f;
        float bb = hi / stride - 0.5f;
        float coord = a + (bb - a) * (((float)s + 0.5f) / 14.0f);
        float valid = (coord > -1.0f && coord < (float)size) ? 1.0f : 0.0f;
        float cc = fminf(fmaxf(coord, 0.0f), (float)(size - 1));
        int i0 = (int)floorf(cc);
        int i1 = min(i0 + 1, size - 1);
        float frac = cc - (float)i0;
        if (isx) { s_ix0[s] = i0; s_ix1[s] = i1; s_wx0[s] = (1.0f - frac) * valid; s_wx1[s] = frac * valid; }
        else     { s_iy0[s] = i0; s_iy1[s] = i1; s_wy0[s] = (1.0f - frac) * valid; s_wy1[s] = frac * valid; }
    }
    __syncthreads();

    uint4* hd = (uint4*)g_p5_hi + (size_t)n * 1568;
    uint4* ld = (uint4*)g_p5_lo + (size_t)n * 1568;

    for (int bin = grp; bin < 49; bin += 8) {
        int by = bin / 7, bx = bin - by * 7;
        float acc[8] = {};
#pragma unroll
        for (int i = 0; i < 2; i++) {
            int sy = by * 2 + i;
            float wy0 = s_wy0[sy], wy1 = s_wy1[sy];
            int row0 = s_iy0[sy] * W;
            int row1 = s_iy1[sy] * W;
#pragma unroll
            for (int j = 0; j < 2; j++) {
                int sx = bx * 2 + j;
                float wx0 = s_wx0[sx], wx1 = s_wx1[sx];
                int xa = s_ix0[sx], xb = s_ix1[sx];
                uint4 v00 = __ldg(base4 + (size_t)(row0 + xa) * 32 + c8);
                uint4 v01 = __ldg(base4 + (size_t)(row0 + xb) * 32 + c8);
                uint4 v10 = __ldg(base4 + (size_t)(row1 + xa) * 32 + c8);
                uint4 v11 = __ldg(base4 + (size_t)(row1 + xb) * 32 + c8);
                acc8(acc, v00, wy0 * wx0);
                acc8(acc, v01, wy0 * wx1);
                acc8(acc, v10, wy1 * wx0);
                acc8(acc, v11, wy1 * wx1);
            }
        }
        uint4 hv, lv;
        pack_hi_lo(acc[0] * 0.25f, acc[1] * 0.25f, hv.x, lv.x);
        pack_hi_lo(acc[2] * 0.25f, acc[3] * 0.25f, hv.y, lv.y);
        pack_hi_lo(acc[4] * 0.25f, acc[5] * 0.25f, hv.z, lv.z);
        pack_hi_lo(acc[6] * 0.25f, acc[7] * 0.25f, hv.w, lv.w);
        hd[bin * 32 + c8] = hv;
        ld[bin * 32 + c8] = lv;
    }
}

// ---------------------------------------------------------------------------
// fc2_w hi/lo split (no permutation)
// ---------------------------------------------------------------------------
__global__ void split_kernel(const float* __restrict__ in,
                             __nv_bfloat16* __restrict__ hi,
                             __nv_bfloat16* __restrict__ lo, int n4) {
    int i = blockIdx.x * blockDim.x + threadIdx.x;
    if (i >= n4) return;
    float4 v = ((const float4*)in)[i];
    uint32_t h0, h1, l0, l1;
    pack_hi_lo(v.x, v.y, h0, l0);
    pack_hi_lo(v.z, v.w, h1, l1);
    ((uint2*)hi)[i] = make_uint2(h0, h1);
    ((uint2*)lo)[i] = make_uint2(l0, l1);
}

// ---------------------------------------------------------------------------
// fc1_w split with bin-major permutation, uint4 stores, float4 staging loads.
// ---------------------------------------------------------------------------
__global__ void split_permute_kernel(const float* __restrict__ in,
                                     __nv_bfloat16* __restrict__ hi,
                                     __nv_bfloat16* __restrict__ lo) {
    __shared__ float sh[3136];
    int j = blockIdx.x;
    int chunk = blockIdx.y;
    const float4* src = (const float4*)(in + (size_t)j * 12544 + chunk * 3136);
    for (int i = threadIdx.x; i < 784; i += 256) ((float4*)sh)[i] = src[i];
    __syncthreads();
    size_t obase = (size_t)j * 12544 + chunk * 64;
    for (int idx = threadIdx.x; idx < 392; idx += 256) {
        int bin = idx >> 3, c8l = idx & 7;
        uint4 hv, lv;
        uint32_t* hp = (uint32_t*)&hv;
        uint32_t* lp = (uint32_t*)&lv;
#pragma unroll
        for (int e = 0; e < 4; e++) {
            float v0 = sh[(c8l * 8 + 2 * e)     * 49 + bin];
            float v1 = sh[(c8l * 8 + 2 * e + 1) * 49 + bin];
            pack_hi_lo(v0, v1, hp[e], lp[e]);
        }
        size_t o = obase + (size_t)bin * 256 + c8l * 8;
        *(uint4*)(hi + o) = hv;
        *(uint4*)(lo + o) = lv;
    }
}

// ---------------------------------------------------------------------------
// FC1 reduce: relu(p0+p1+p2+p3+bias) -> bf16 hi/lo.
// ---------------------------------------------------------------------------
__global__ void reduce_split_kernel(const float* __restrict__ part,
                                    const float* __restrict__ bias,
                                    __nv_bfloat16* __restrict__ hi,
                                    __nv_bfloat16* __restrict__ lo) {
    int i = blockIdx.x * 256 + threadIdx.x;
    float4 a = ((const float4*)part)[i];
    float4 b = ((const float4*)(part + 1048576))[i];
    float4 c = ((const float4*)(part + 2097152))[i];
    float4 d = ((const float4*)(part + 3145728))[i];
    float4 bs = ((const float4*)bias)[i & 255];
    float v0 = fmaxf(a.x + b.x + c.x + d.x + bs.x, 0.0f);
    float v1 = fmaxf(a.y + b.y + c.y + d.y + bs.y, 0.0f);
    float v2 = fmaxf(a.z + b.z + c.z + d.z + bs.z, 0.0f);
    float v3 = fmaxf(a.w + b.w + c.w + d.w + bs.w, 0.0f);
    uint32_t h0, h1, l0, l1;
    pack_hi_lo(v0, v1, h0, l0);
    pack_hi_lo(v2, v3, h1, l1);
    ((uint2*)hi)[i] = make_uint2(h0, h1);
    ((uint2*)lo)[i] = make_uint2(l0, l1);
}

// ---------------------------------------------------------------------------
// GEMM: 128x256 tile, BK=64, hi/lo bf16 (3 products), 2-stage ping-pong with
// lagged MMA wait, blockIdx.z = split-K slice. Raw fp32 partial out.
// Stage layout: Ah(16K) Al(16K) Bh(32K) Bl(32K) = 96KB; 2 stages.
// ---------------------------------------------------------------------------
__device__ __forceinline__ void load_rows(uint32_t s_tile, const __nv_bfloat16* g,
                                          int ldK, int tid, int nrows) {
    for (int gid = tid; gid < nrows * 8; gid += 256) {
        int row = gid >> 3, c16 = gid & 7;
        uint32_t dst = s_tile + row * 128 + ((c16 ^ (row & 7)) << 4);
        const char* src = (const char*)(g + (size_t)row * ldK) + (c16 << 4);
        asm volatile("cp.async.cg.shared.global [%0], [%1], 16;" :: "r"(dst), "l"(src) : "memory");
    }
}

__global__ __launch_bounds__(256, 1) void gemm_tc(
    const __nv_bfloat16* __restrict__ Ahi, const __nv_bfloat16* __restrict__ Alo,
    const __nv_bfloat16* __restrict__ Bhi, const __nv_bfloat16* __restrict__ Blo,
    float* __restrict__ Cf,
    int N, int K, int ldK) {
    extern __shared__ char dsm[];
    int tid = threadIdx.x;
    int bm = blockIdx.y * 128, bn = blockIdx.x * 256;
    int z = blockIdx.z;
    size_t koff = (size_t)z * K;

    const __nv_bfloat16* Ah = Ahi + (size_t)bm * ldK + koff;
    const __nv_bfloat16* Al = Alo + (size_t)bm * ldK + koff;
    const __nv_bfloat16* Bh = Bhi + (size_t)bn * ldK + koff;
    const __nv_bfloat16* Bl = Blo + (size_t)bn * ldK + koff;
    float* Cz = Cf + (size_t)z * (size_t)(gridDim.y * 128) * N;

#if HAS_TCGEN05
    __shared__ uint32_t s_tmem;
    __shared__ uint64_t s_mbar[2];

    uint32_t sbase = (smem_u32(dsm) + 1023u) & ~1023u;
    int wid = tid >> 5, lid = tid & 31;

    uint32_t mb[2] = { smem_u32(&s_mbar[0]), smem_u32(&s_mbar[1]) };

    if (wid == 0) TCGEN05_ALLOC(smem_u32(&s_tmem), 256);
    if (tid == 0) { MBARRIER_INIT(mb[0], 1); MBARRIER_INIT(mb[1], 1); }
    __syncthreads();
    uint32_t tmem = s_tmem;
    if (wid == 0) TCGEN05_RELINQ();

    const int nblk = K >> 6;
    const uint32_t STG = 98304u;  // 96KB per stage

    // prologue: blk0 -> stage0, blk1 -> stage1
#pragma unroll
    for (int p = 0; p < 2; p++) {
        uint32_t st = sbase + (uint32_t)p * STG;
        load_rows(st,          Ah + p * 64, ldK, tid, 128);
        load_rows(st + 16384u, Al + p * 64, ldK, tid, 128);
        load_rows(st + 32768u, Bh + p * 64, ldK, tid, 256);
        load_rows(st + 65536u, Bl + p * 64, ldK, tid, 256);
        CP_COMMIT();
    }

    int ph[2] = {0, 0};
    for (int i = 0; i < nblk; i++) {
        int s = i & 1;
        CP_WAIT_0();            // blk i's loads done (blk i+1 not committed yet)
        __syncthreads();
        if (tid < 32) {
            if (elect_one()) {
                FENCE_PROXY_ASYNC();
                uint32_t st = sbase + (uint32_t)s * STG;
                uint64_t dah = MAKE_DESC(st);
                uint64_t dal = MAKE_DESC(st + 16384u);
                uint64_t dbh = MAKE_DESC(st + 32768u);
                uint64_t dbl = MAKE_DESC(st + 65536u);
                bool en = (i > 0);
#pragma unroll
                for (int k = 0; k < 4; k++) {
                    mma_f16_ss(tmem, dah + k * 2, dbh + k * 2, GEMM_IDESC, en); en = true;
                    mma_f16_ss(tmem, dah + k * 2, dbl + k * 2, GEMM_IDESC, true);
                    mma_f16_ss(tmem, dal + k * 2, dbh + k * 2, GEMM_IDESC, true);
                }
                TCGEN05_COMMIT(mb[s]);
            }
        }
        // refill stage s^1 (held blk i-1) with blk i+1 after MMA(i-1) completes
        if (i >= 1) {
            int so = s ^ 1;
            MBARRIER_WAIT_PARITY(mb[so], ph[so]);
            ph[so] ^= 1;
            if (i + 1 < nblk) {
                uint32_t st = sbase + (uint32_t)so * STG;
                int j = i + 1;
                load_rows(st,          Ah + j * 64, ldK, tid, 128);
                load_rows(st + 16384u, Al + j * 64, ldK, tid, 128);
                load_rows(st + 32768u, Bh + j * 64, ldK, tid, 256);
                load_rows(st + 65536u, Bl + j * 64, ldK, tid, 256);
                CP_COMMIT();
            }
        }
        __syncthreads();
    }

    {
        int lastS = (nblk - 1) & 1;
        MBARRIER_WAIT_PARITY(mb[lastS], ph[lastS]);
    }
    TCGEN05_FENCE_AFTER();

    if (tid < 128) {
        int row = bm + wid * 32 + lid;
#pragma unroll
        for (int cb = 0; cb < 256; cb += 32) {
            uint32_t rr[32];
            TCGEN05_LD_X32(rr, tmem + cb);
            TCGEN05_WAIT_LD();
            float* cd = Cz + (size_t)row * N + bn + cb;
#pragma unroll
            for (int c = 0; c < 32; c++)
                cd[c] = __uint_as_float(rr[c]);
        }
        TCGEN05_FENCE_BEFORE();
    }
    __syncthreads();
    if (wid == 0) TCGEN05_DEALLOC(tmem, 256);

#else  // ---------------- SIMT fallback (baseline compute_103 pass) ---------
    float* As = (float*)dsm;
    float* Bs = As + 16 * 132;

    int tr = (tid >> 4) * 8;
    int tc = (tid & 15) * 8;

    for (int half = 0; half < 2; half++) {
        int bn2 = bn + half * 128;
        float acc[8][8] = {};
        for (int k0 = 0; k0 < K; k0 += 16) {
#pragma unroll
            for (int e = 0; e < 8; e++) {
                int idx = tid * 8 + e;
                int kk = idx >> 7, rr = idx & 127;
                As[kk * 132 + rr] = __bfloat162float(Ah[(size_t)rr * ldK + k0 + kk]) +
                                    __bfloat162float(Al[(size_t)rr * ldK + k0 + kk]);
                Bs[kk * 132 + rr] = __bfloat162float(Bh[(size_t)(half * 128 + rr) * ldK + k0 + kk]) +
                                    __bfloat162float(Bl[(size_t)(half * 128 + rr) * ldK + k0 + kk]);
            }
            __syncthreads();
#pragma unroll
            for (int k = 0; k < 16; k++) {
                float ra[8], rb[8];
#pragma unroll
                for (int i = 0; i < 8; i++) ra[i] = As[k * 132 + tr + i];
#pragma unroll
                for (int j = 0; j < 8; j++) rb[j] = Bs[k * 132 + tc + j];
#pragma unroll
                for (int i = 0; i < 8; i++)
#pragma unroll
                    for (int j = 0; j < 8; j++) acc[i][j] += ra[i] * rb[j];
            }
            __syncthreads();
        }
#pragma unroll
        for (int i = 0; i < 8; i++)
#pragma unroll
            for (int j = 0; j < 8; j++)
                Cz[(size_t)(bm + tr + i) * N + bn2 + tc + j] = acc[i][j];
    }
#endif
}

// ---------------------------------------------------------------------------
// Projection with fused FC2 reduce: sh = relu(Σ4 partials + fc2_b), then
// out[n, j] = dot(sh, p_w[j,:]) + p_b[j], j < 20.
// ---------------------------------------------------------------------------
__global__ void proj_kernel(const float* __restrict__ part,
                            const float* __restrict__ fc2_b,
                            const float* __restrict__ p_w,
                            const float* __restrict__ p_b,
                            float* __restrict__ out, int NJ) {
    __shared__ float sh[1024];
    __shared__ float red[32][4];
    int n = blockIdx.x;
    int t = threadIdx.x;   // 128
    for (int i = t; i < 256; i += 128) {   // float4 over the 1024-row
        float4 a = ((const float4*)(part + (size_t)n * 1024))[i];
        float4 b = ((const float4*)(part + 1048576 + (size_t)n * 1024))[i];
        float4 c = ((const float4*)(part + 2097152 + (size_t)n * 1024))[i];
        float4 d = ((const float4*)(part + 3145728 + (size_t)n * 1024))[i];
        float4 bs = ((const float4*)fc2_b)[i];
        float4 o;
        o.x = fmaxf(a.x + b.x + c.x + d.x + bs.x, 0.0f);
        o.y = fmaxf(a.y + b.y + c.y + d.y + bs.y, 0.0f);
        o.z = fmaxf(a.z + b.z + c.z + d.z + bs.z, 0.0f);
        o.w = fmaxf(a.w + b.w + c.w + d.w + bs.w, 0.0f);
        ((float4*)sh)[i] = o;
    }
    __syncthreads();
    int j = t >> 2, ck = t & 3;
    if (j < NJ) {
        const float* wrow = p_w + (size_t)j * 1024 + ck * 256;
        const float* sv = sh + ck * 256;
        float s = 0.0f;
#pragma unroll 8
        for (int k = 0; k < 256; k++) s += sv[k] * wrow[k];
        red[j][ck] = s;
    }
    __syncthreads();
    if (t < NJ)
        out[(size_t)n * NJ + t] = red[t][0] + red[t][1] + red[t][2] + red[t][3] + p_b[t];
}

// ---------------------------------------------------------------------------
extern "C" void kernel_launch(void* const* d_in, const int* in_sizes, int n_in,
                              void* d_out, int out_size) {
    const float* fm0   = (const float*)d_in[0];
    const float* fm1   = (const float*)d_in[1];
    const float* fm2   = (const float*)d_in[2];
    const float* fm3   = (const float*)d_in[3];
    const float* rois  = (const float*)d_in[4];
    const float* fc1_w = (const float*)d_in[5];
    const float* fc1_b = (const float*)d_in[6];
    const float* fc2_w = (const float*)d_in[7];
    const float* fc2_b = (const float*)d_in[8];
    const float* p_w   = (const float*)d_in[9];
    const float* p_b   = (const float*)d_in[10];
    float* out = (float*)d_out;

    int nrois = in_sizes[4] / 5;   // 1024
    int nj = out_size / nrois;     // 20

    static cudaStream_t s2 = nullptr;
    static cudaEvent_t evF = nullptr, evJ1 = nullptr, evJ2 = nullptr;
    if (!s2) {
        cudaStreamCreateWithFlags(&s2, cudaStreamNonBlocking);
        cudaEventCreateWithFlags(&evF, cudaEventDisableTiming);
        cudaEventCreateWithFlags(&evJ1, cudaEventDisableTiming);
        cudaEventCreateWithFlags(&evJ2, cudaEventDisableTiming);
    }

    __nv_bfloat16 *w1h, *w1l, *w2h, *w2l, *p5h, *p5l, *f1h, *f1l;
    float* partp;
    cudaGetSymbolAddress((void**)&w1h, g_w1_hi);
    cudaGetSymbolAddress((void**)&w1l, g_w1_lo);
    cudaGetSymbolAddress((void**)&w2h, g_w2_hi);
    cudaGetSymbolAddress((void**)&w2l, g_w2_lo);
    cudaGetSymbolAddress((void**)&p5h, g_p5_hi);
    cudaGetSymbolAddress((void**)&p5l, g_p5_lo);
    cudaGetSymbolAddress((void**)&f1h, g_fc1_hi);
    cudaGetSymbolAddress((void**)&f1l, g_fc1_lo);
    cudaGetSymbolAddress((void**)&partp, g_part);

    // Fork: weight splits concurrent with transpose + ROI.
    // evJ1 gates GEMM1 (needs w1 only); evJ2 gates GEMM2 (needs w2).
    cudaEventRecord(evF, 0);
    cudaStreamWaitEvent(s2, evF, 0);
    split_permute_kernel<<<dim3(1024, 4), 256, 0, s2>>>(fc1_w, w1h, w1l);
    cudaEventRecord(evJ1, s2);
    split_kernel<<<(1024 * 1024 / 4 + 255) / 256, 256, 0, s2>>>(fc2_w, w2h, w2l, 1024 * 1024 / 4);
    cudaEventRecord(evJ2, s2);

    // Main: all-level transpose, then ROIAlign.
    nchw2nhwc_all_kernel<<<dim3(319, 8, 2), 256>>>(fm0, fm1, fm2, fm3);
    roi_align_kernel<<<nrois, 256>>>(rois);

    const int GEMM_SMEM = 1024 + 2 * 98304;  // 197632 (2-stage, 96KB/stage)
    cudaFuncSetAttribute(gemm_tc,
                         cudaFuncAttributeMaxDynamicSharedMemorySize, GEMM_SMEM);

    // FC1 split-K4: partials then reduce(+bias+relu+split).
    cudaStreamWaitEvent(0, evJ1, 0);
    gemm_tc<<<dim3(4, nrois / 128, 4), 256, GEMM_SMEM>>>(
        p5h, p5l, w1h, w1l, partp, 1024, 3136, 12544);
    reduce_split_kernel<<<1024, 256>>>(partp, fc1_b, f1h, f1l);

    // FC2 split-K4: partials; reduce fused into proj.
    cudaStreamWaitEvent(0, evJ2, 0);
    gemm_tc<<<dim3(4, nrois / 128, 4), 256, GEMM_SMEM>>>(
        f1h, f1l, w2h, w2l, partp, 1024, 256, 1024);

    // Projection (+ fused FC2 reduce)
    proj_kernel<<<nrois, 128>>>(partp, fc2_b, p_w, p_b, out, nj);
}

// round 14
// speedup vs baseline: 1.1013x; 1.1013x over previous
#include <cuda_runtime.h>
#include <cuda_bf16.h>
#include <cuda_fp16.h>
#include <cstdint>

// ---------------------------------------------------------------------------
// Shapes: B=2, C=256, Im 768x1280, strides {4,8,16,32}, N=1024 rois
// pool5 D = 256*49 = 12544 (K-major: d = ch*49 + bin)
// fc1: 12544->1024 relu; fc2: 1024->1024 relu; proj->20
// ---------------------------------------------------------------------------

#define NCH 256

#if defined(__CUDA_ARCH__) && defined(__CUDA_ARCH_FEAT_SM103_ALL)
#define HAS_TCGEN05 1
#else
#define HAS_TCGEN05 0
#endif

__device__ __half g_nhwc[41779200];          // fp16 NHWC staging
__device__ __nv_bfloat16 g_p5_hi[1024 * 12544];
__device__ __nv_bfloat16 g_p5_lo[1024 * 12544];
__device__ __nv_bfloat16 g_w1_hi[1024 * 12544];
__device__ __nv_bfloat16 g_w1_lo[1024 * 12544];
__device__ __nv_bfloat16 g_fc1_hi[1024 * 1024];
__device__ __nv_bfloat16 g_fc1_lo[1024 * 1024];
__device__ __nv_bfloat16 g_w2_hi[1024 * 1024];
__device__ __nv_bfloat16 g_w2_lo[1024 * 1024];
__device__ float g_part[2 * 1024 * 1024];    // split-K2 partials

__constant__ size_t c_lvl_off[4] = {0, 31457280, 39321600, 41287680};

// ============================ PTX helpers ==================================
__device__ __forceinline__ uint32_t smem_u32(const void* p) {
    uint32_t a;
    asm("{ .reg .u64 t; cvta.to.shared.u64 t, %1; cvt.u32.u64 %0, t; }" : "=r"(a) : "l"(p));
    return a;
}
__device__ __forceinline__ uint32_t elect_one() {
    uint32_t p;
    asm volatile("{\n\t.reg .pred p;\n\telect.sync _|p, 0xFFFFFFFF;\n\tselp.b32 %0, 1, 0, p;\n\t}" : "=r"(p));
    return p;
}
#define MBARRIER_INIT(addr, cnt) \
    asm volatile("mbarrier.init.shared.b64 [%0], %1;" :: "r"(addr), "r"(cnt) : "memory")
#define MBARRIER_WAIT_PARITY(addr, par) do {                                          \
    uint32_t _m = (addr); uint32_t _p = (par); uint32_t _d;                           \
    asm volatile("{\n\t.reg .pred p;\n\t"                                             \
        "mbarrier.try_wait.parity.acquire.cta.shared::cta.b64 p, [%1], %2;\n\t"       \
        "selp.b32 %0, 1, 0, p;\n\t}" : "=r"(_d) : "r"(_m), "r"(_p) : "memory");       \
    if (!_d) {                                                                        \
        asm volatile("{\n\t.reg .pred P1;\n\t"                                        \
            "WL_%=:\n\t"                                                              \
            "mbarrier.try_wait.parity.acquire.cta.shared::cta.b64 P1, [%0], %1, 0x989680;\n\t" \
            "@P1 bra.uni WD_%=;\n\tbra.uni WL_%=;\n\tWD_%=:\n\t}"                     \
            :: "r"(_m), "r"(_p) : "memory");                                          \
    } } while (0)
#define FENCE_PROXY_ASYNC() asm volatile("fence.proxy.async.shared::cta;" ::: "memory")
#define CP_COMMIT() asm volatile("cp.async.commit_group;" ::: "memory")
#define CP_WAIT_1() asm volatile("cp.async.wait_group 1;" ::: "memory")

#if HAS_TCGEN05
#define TCGEN05_ALLOC(sa, n) \
    asm volatile("tcgen05.alloc.cta_group::1.sync.aligned.shared::cta.b32 [%0], %1;" :: "r"(sa), "r"(n) : "memory")
#define TCGEN05_DEALLOC(t, n) \
    asm volatile("tcgen05.dealloc.cta_group::1.sync.aligned.b32 %0, %1;" :: "r"(t), "r"(n))
#define TCGEN05_RELINQ() \
    asm volatile("tcgen05.relinquish_alloc_permit.cta_group::1.sync.aligned;")
#define TCGEN05_COMMIT(mb) \
    asm volatile("tcgen05.commit.cta_group::1.mbarrier::arrive::one.shared::cluster.b64 [%0];" :: "r"(mb) : "memory")
#define TCGEN05_FENCE_AFTER()  asm volatile("tcgen05.fence::after_thread_sync;" ::: "memory")
#define TCGEN05_FENCE_BEFORE() asm volatile("tcgen05.fence::before_thread_sync;" ::: "memory")
#define TCGEN05_WAIT_LD() asm volatile("tcgen05.wait::ld.sync.aligned;" ::: "memory")

#define TCGEN05_LD_X32(r, ta)                                                          \
    asm volatile("tcgen05.ld.sync.aligned.32x32b.x32.b32 "                             \
        "{%0, %1, %2, %3, %4, %5, %6, %7, %8, %9, %10, %11, %12, %13, %14, %15, "      \
        " %16, %17, %18, %19, %20, %21, %22, %23, %24, %25, %26, %27, %28, %29, %30, %31}, [%32];" \
        : "=r"((r)[0]), "=r"((r)[1]), "=r"((r)[2]), "=r"((r)[3]),                      \
          "=r"((r)[4]), "=r"((r)[5]), "=r"((r)[6]), "=r"((r)[7]),                      \
          "=r"((r)[8]), "=r"((r)[9]), "=r"((r)[10]), "=r"((r)[11]),                    \
          "=r"((r)[12]), "=r"((r)[13]), "=r"((r)[14]), "=r"((r)[15]),                  \
          "=r"((r)[16]), "=r"((r)[17]), "=r"((r)[18]), "=r"((r)[19]),                  \
          "=r"((r)[20]), "=r"((r)[21]), "=r"((r)[22]), "=r"((r)[23]),                  \
          "=r"((r)[24]), "=r"((r)[25]), "=r"((r)[26]), "=r"((r)[27]),                  \
          "=r"((r)[28]), "=r"((r)[29]), "=r"((r)[30]), "=r"((r)[31])                   \
        : "r"(ta))

__device__ __forceinline__ void mma_f16_ss(uint32_t d, uint64_t a, uint64_t b,
                                           uint32_t idesc, bool en) {
    uint32_t e = en ? 1u : 0u;
    asm volatile(
        "{\n\t.reg .pred p;\n\tsetp.ne.u32 p, %4, 0;\n\t"
        "tcgen05.mma.cta_group::1.kind::f16 [%0], %1, %2, %3, {%5, %5, %5, %5}, p;\n\t}"
        :: "r"(d), "l"(a), "l"(b), "r"(idesc), "r"(e), "r"(0u) : "memory");
}
#endif  // HAS_TCGEN05

// SW128 K-major descriptor: layout=2, version=1, SBO=64, LBO=1
static constexpr uint64_t DESC_BASE_SW128 =
    (uint64_t(2) << 61) | (uint64_t(1) << 46) | (uint64_t(64) << 32) | (uint64_t(1) << 16);
#define MAKE_DESC(a) (DESC_BASE_SW128 | ((uint64_t)((a) >> 4) & 0x3FFF))

// idesc kind::f16: F32 accum, BF16 a/b, M=128, N=128
static constexpr uint32_t GEMM_IDESC =
    (1u << 4) | (1u << 7) | (1u << 10) | ((128u / 8u) << 17) | ((128u / 16u) << 24);

__device__ __forceinline__ void pack_hi_lo(float v0, float v1, uint32_t& h, uint32_t& l) {
    asm("cvt.rn.bf16x2.f32 %0, %1, %2;" : "=r"(h) : "f"(v1), "f"(v0));
    float l0 = v0 - __uint_as_float(h << 16);
    float l1 = v1 - __uint_as_float(h & 0xffff0000u);
    asm("cvt.rn.bf16x2.f32 %0, %1, %2;" : "=r"(l) : "f"(l1), "f"(l0));
}

// ---------------------------------------------------------------------------
// All-level NCHW fp32 -> NHWC fp16 transpose in ONE launch.
// ---------------------------------------------------------------------------
__global__ void nchw2nhwc_all_kernel(const float* __restrict__ fm0,
                                     const float* __restrict__ fm1,
                                     const float* __restrict__ fm2,
                                     const float* __restrict__ fm3) {
    __shared__ float tile[8][32][33];
    int bx = blockIdx.x;
    int lvl, bl;
    if      (bx < 240) { lvl = 0; bl = bx; }
    else if (bx < 300) { lvl = 1; bl = bx - 240; }
    else if (bx < 315) { lvl = 2; bl = bx - 300; }
    else               { lvl = 3; bl = bx - 315; }
    int HW = 61440 >> (2 * lvl);
    const float* in = (lvl == 0) ? fm0 : (lvl == 1) ? fm1 : (lvl == 2) ? fm2 : fm3;
    size_t off = c_lvl_off[lvl];

    int b = blockIdx.z;
    int c0 = blockIdx.y * 32;
    int t = threadIdx.x;            // 256
    int cr  = t >> 3;               // 0..31
    int f4  = t & 7;                // 0..7

    int hwbase = bl * 256;
    int nrep = (HW - hwbase + 31) >> 5;      // uniform; 1..8
    if (nrep > 8) nrep = 8;

    float4 v[8];
#pragma unroll
    for (int rep = 0; rep < 8; rep++)
        if (rep < nrep)
            v[rep] = *((const float4*)(in + ((size_t)b * NCH + c0 + cr) * HW + hwbase + rep * 32) + f4);

#pragma unroll
    for (int rep = 0; rep < 8; rep++)
        if (rep < nrep) {
            tile[rep][f4 * 4 + 0][cr] = v[rep].x;
            tile[rep][f4 * 4 + 1][cr] = v[rep].y;
            tile[rep][f4 * 4 + 2][cr] = v[rep].z;
            tile[rep][f4 * 4 + 3][cr] = v[rep].w;
        }
    __syncthreads();

#pragma unroll
    for (int rep = 0; rep < 8; rep++)
        if (rep < nrep) {
            half2 a = __floats2half2_rn(tile[rep][cr][f4 * 4 + 0], tile[rep][cr][f4 * 4 + 1]);
            half2 c = __floats2half2_rn(tile[rep][cr][f4 * 4 + 2], tile[rep][cr][f4 * 4 + 3]);
            uint2 o;
            o.x = *(uint32_t*)&a;
            o.y = *(uint32_t*)&c;
            *(uint2*)(g_nhwc + off + ((size_t)b * HW + hwbase + rep * 32 + cr) * NCH + c0 + f4 * 4) = o;
        }
}

// ---------------------------------------------------------------------------
// ROIAlign from fp16 NHWC: 32 channel-octets x 8 bin-groups, fp32 math,
// smem staging for coalesced K-major (ch*49+bin) hi/lo output.
// ---------------------------------------------------------------------------
__device__ __forceinline__ void acc8(float* acc, uint4 v, float w) {
    half2* h = (half2*)&v;
#pragma unroll
    for (int e = 0; e < 4; e++) {
        float2 f = __half22float2(h[e]);
        acc[2 * e]     += w * f.x;
        acc[2 * e + 1] += w * f.y;
    }
}

__global__ void roi_align_kernel(const float* __restrict__ rois) {
    extern __shared__ float shbuf[];  // 12544 floats, [channel*49 + bin]
    __shared__ int   s_ix0[14], s_ix1[14], s_iy0[14], s_iy1[14];
    __shared__ float s_wx0[14], s_wx1[14], s_wy0[14], s_wy1[14];

    int n = blockIdx.x;
    int tid = threadIdx.x;
    int c8  = tid & 31;   // channel octet 0..31
    int grp = tid >> 5;   // 0..7

    const float* r = rois + (size_t)n * 5;
    int   b  = (int)r[0];
    float x1 = r[1], y1 = r[2], x2 = r[3], y2 = r[4];

    float w = x2 - x1, h = y2 - y1;
    float kf = floorf(4.0f + log2f(sqrtf(fmaxf(w * h, 1e-6f)) / 224.0f));
    kf = fminf(fmaxf(kf, 2.0f), 5.0f);
    int lvl = (int)kf - 2;

    float stride = (float)(4 << lvl);
    int H = 768 >> (lvl + 2);
    int W = 1280 >> (lvl + 2);
    const uint4* base4 = (const uint4*)(g_nhwc + c_lvl_off[lvl] + (size_t)b * H * W * NCH);

    if (tid < 28) {
        bool isx = tid < 14;
        int  s   = isx ? tid : tid - 14;
        float lo = isx ? x1 : y1;
        float hi = isx ? x2 : y2;
        int size = isx ? W : H;
        float a = lo / stride - 0.5f;
        float bb = hi / stride - 0.5f;
        float coord = a + (bb - a) * (((float)s + 0.5f) / 14.0f);
        float valid = (coord > -1.0f && coord < (float)size) ? 1.0f : 0.0f;
        float cc = fminf(fmaxf(coord, 0.0f), (float)(size - 1));
        int i0 = (int)floorf(cc);
        int i1 = min(i0 + 1, size - 1);
        float frac = cc - (float)i0;
        if (isx) { s_ix0[s] = i0; s_ix1[s] = i1; s_wx0[s] = (1.0f - frac) * valid; s_wx1[s] = frac * valid; }
        else     { s_iy0[s] = i0; s_iy1[s] = i1; s_wy0[s] = (1.0f - frac) * valid; s_wy1[s] = frac * valid; }
    }
    __syncthreads();

    for (int bin = grp; bin < 49; bin += 8) {
        int by = bin / 7, bx = bin - by * 7;
        float acc[8] = {};
#pragma unroll
        for (int i = 0; i < 2; i++) {
            int sy = by * 2 + i;
            float wy0 = s_wy0[sy], wy1 = s_wy1[sy];
            int row0 = s_iy0[sy] * W;
            int row1 = s_iy1[sy] * W;
#pragma unroll
            for (int j = 0; j < 2; j++) {
                int sx = bx * 2 + j;
                float wx0 = s_wx0[sx], wx1 = s_wx1[sx];
                int xa = s_ix0[sx], xb = s_ix1[sx];
                uint4 v00 = __ldg(base4 + (size_t)(row0 + xa) * 32 + c8);
                uint4 v01 = __ldg(base4 + (size_t)(row0 + xb) * 32 + c8);
                uint4 v10 = __ldg(base4 + (size_t)(row1 + xa) * 32 + c8);
                uint4 v11 = __ldg(base4 + (size_t)(row1 + xb) * 32 + c8);
                acc8(acc, v00, wy0 * wx0);
                acc8(acc, v01, wy0 * wx1);
                acc8(acc, v10, wy1 * wx0);
                acc8(acc, v11, wy1 * wx1);
            }
        }
        int ch = c8 * 8;
#pragma unroll
        for (int e = 0; e < 8; e++)
            shbuf[(ch + e) * 49 + bin] = acc[e] * 0.25f;
    }
    __syncthreads();

    uint32_t* hd = (uint32_t*)(g_p5_hi + (size_t)n * 12544);
    uint32_t* ld = (uint32_t*)(g_p5_lo + (size_t)n * 12544);
    for (int i = tid; i < 6272; i += 256) {
        float v0 = shbuf[2 * i], v1 = shbuf[2 * i + 1];
        uint32_t hh, ll;
        pack_hi_lo(v0, v1, hh, ll);
        hd[i] = hh; ld[i] = ll;
    }
}

// ---------------------------------------------------------------------------
// fp32 -> bf16 hi/lo split (both weight matrices)
// ---------------------------------------------------------------------------
__global__ void split_kernel(const float* __restrict__ in,
                             __nv_bfloat16* __restrict__ hi,
                             __nv_bfloat16* __restrict__ lo, int n4) {
    int i = blockIdx.x * blockDim.x + threadIdx.x;
    if (i >= n4) return;
    float4 v = ((const float4*)in)[i];
    uint32_t h0, h1, l0, l1;
    pack_hi_lo(v.x, v.y, h0, l0);
    pack_hi_lo(v.z, v.w, h1, l1);
    ((uint2*)hi)[i] = make_uint2(h0, h1);
    ((uint2*)lo)[i] = make_uint2(l0, l1);
}

// ---------------------------------------------------------------------------
// FC1 reduce: relu(p0 + p1 + bias) -> bf16 hi/lo.
// ---------------------------------------------------------------------------
__global__ void reduce_split_kernel(const float* __restrict__ part,
                                    const float* __restrict__ bias,
                                    __nv_bfloat16* __restrict__ hi,
                                    __nv_bfloat16* __restrict__ lo) {
    int i = blockIdx.x * 256 + threadIdx.x;   // float4 index, 262144 total
    float4 a = ((const float4*)part)[i];
    float4 b = ((const float4*)(part + 1048576))[i];
    float4 bs = ((const float4*)bias)[i & 255];
    float v0 = fmaxf(a.x + b.x + bs.x, 0.0f);
    float v1 = fmaxf(a.y + b.y + bs.y, 0.0f);
    float v2 = fmaxf(a.z + b.z + bs.z, 0.0f);
    float v3 = fmaxf(a.w + b.w + bs.w, 0.0f);
    uint32_t h0, h1, l0, l1;
    pack_hi_lo(v0, v1, h0, l0);
    pack_hi_lo(v2, v3, h1, l1);
    ((uint2*)hi)[i] = make_uint2(h0, h1);
    ((uint2*)lo)[i] = make_uint2(l0, l1);
}

// ---------------------------------------------------------------------------
// GEMM: C[M,N] = A[M,K] @ B[N,K]^T, tcgen05 hi/lo bf16, 128x128 tile, BK=64,
// 3-stage cp.async pipeline with lagged MMA wait. blockIdx.z = split-K slice.
// Raw fp32 partial out.
// ---------------------------------------------------------------------------
__device__ __forceinline__ void load_tile16(uint32_t s_tile, const __nv_bfloat16* g,
                                            int ldK, int tid) {
#pragma unroll
    for (int q = 0; q < 4; q++) {
        int gid = tid + q * 256;
        int row = gid >> 3, c16 = gid & 7;
        uint32_t dst = s_tile + row * 128 + ((c16 ^ (row & 7)) << 4);
        const char* src = (const char*)(g + (size_t)row * ldK) + (c16 << 4);
        asm volatile("cp.async.cg.shared.global [%0], [%1], 16;" :: "r"(dst), "l"(src) : "memory");
    }
}

__global__ __launch_bounds__(256, 1) void gemm_tc(
    const __nv_bfloat16* __restrict__ Ahi, const __nv_bfloat16* __restrict__ Alo,
    const __nv_bfloat16* __restrict__ Bhi, const __nv_bfloat16* __restrict__ Blo,
    float* __restrict__ Cf,
    int N, int K, int ldK) {
    extern __shared__ char dsm[];
    int tid = threadIdx.x;
    int bm = blockIdx.y * 128, bn = blockIdx.x * 128;
    int z = blockIdx.z;
    size_t koff = (size_t)z * K;

    const __nv_bfloat16* Ah = Ahi + (size_t)bm * ldK + koff;
    const __nv_bfloat16* Al = Alo + (size_t)bm * ldK + koff;
    const __nv_bfloat16* Bh = Bhi + (size_t)bn * ldK + koff;
    const __nv_bfloat16* Bl = Blo + (size_t)bn * ldK + koff;
    float* Cz = Cf + (size_t)z * (size_t)(gridDim.y * 128) * N;

#if HAS_TCGEN05
    __shared__ uint32_t s_tmem;
    __shared__ uint64_t s_mbar[3];

    uint32_t sbase = (smem_u32(dsm) + 1023u) & ~1023u;
    int wid = tid >> 5, lid = tid & 31;

    uint32_t mb[3] = { smem_u32(&s_mbar[0]), smem_u32(&s_mbar[1]), smem_u32(&s_mbar[2]) };

    if (wid == 0) TCGEN05_ALLOC(smem_u32(&s_tmem), 128);
    if (tid == 0) { MBARRIER_INIT(mb[0], 1); MBARRIER_INIT(mb[1], 1); MBARRIER_INIT(mb[2], 1); }
    __syncthreads();
    uint32_t tmem = s_tmem;
    if (wid == 0) TCGEN05_RELINQ();

    const int nblk = K >> 6;

#pragma unroll
    for (int p = 0; p < 2; p++) {
        uint32_t st = sbase + (uint32_t)p * 65536u;
        load_tile16(st,          Ah + p * 64, ldK, tid);
        load_tile16(st + 16384u, Al + p * 64, ldK, tid);
        load_tile16(st + 32768u, Bh + p * 64, ldK, tid);
        load_tile16(st + 49152u, Bl + p * 64, ldK, tid);
        CP_COMMIT();
    }

    int ph[3] = {0, 0, 0};
    int s = 0, sp = 2;
    for (int i = 0; i < nblk; i++) {
        CP_WAIT_1();
        __syncthreads();
        if (tid < 32) {
            if (elect_one()) {
                FENCE_PROXY_ASYNC();
                uint32_t st = sbase + (uint32_t)s * 65536u;
                uint64_t dah = MAKE_DESC(st);
                uint64_t dal = MAKE_DESC(st + 16384u);
                uint64_t dbh = MAKE_DESC(st + 32768u);
                uint64_t dbl = MAKE_DESC(st + 49152u);
                bool en = (i > 0);
#pragma unroll
                for (int k = 0; k < 4; k++) {
                    mma_f16_ss(tmem, dah + k * 2, dbh + k * 2, GEMM_IDESC, en); en = true;
                    mma_f16_ss(tmem, dah + k * 2, dbl + k * 2, GEMM_IDESC, true);
                    mma_f16_ss(tmem, dal + k * 2, dbh + k * 2, GEMM_IDESC, true);
                }
                TCGEN05_COMMIT(mb[s]);
            }
        }
        if (i >= 1) {
            MBARRIER_WAIT_PARITY(mb[sp], ph[sp]);
            ph[sp] ^= 1;
            if (i + 2 < nblk) {
                uint32_t st = sbase + (uint32_t)sp * 65536u;
                int j = i + 2;
                load_tile16(st,          Ah + j * 64, ldK, tid);
                load_tile16(st + 16384u, Al + j * 64, ldK, tid);
                load_tile16(st + 32768u, Bh + j * 64, ldK, tid);
                load_tile16(st + 49152u, Bl + j * 64, ldK, tid);
            }
        } else if (nblk > 2) {
            uint32_t st = sbase + 2u * 65536u;
            load_tile16(st,          Ah + 2 * 64, ldK, tid);
            load_tile16(st + 16384u, Al + 2 * 64, ldK, tid);
            load_tile16(st + 32768u, Bh + 2 * 64, ldK, tid);
            load_tile16(st + 49152u, Bl + 2 * 64, ldK, tid);
        }
        CP_COMMIT();
        sp = s;
        s = (s == 2) ? 0 : s + 1;
    }

    {
        int lastS = (nblk - 1) % 3;
        MBARRIER_WAIT_PARITY(mb[lastS], ph[lastS]);
    }
    TCGEN05_FENCE_AFTER();

    if (tid < 128) {
        int row = bm + wid * 32 + lid;
#pragma unroll
        for (int cb = 0; cb < 128; cb += 32) {
            uint32_t rr[32];
            TCGEN05_LD_X32(rr, tmem + cb);
            TCGEN05_WAIT_LD();
            float* cd = Cz + (size_t)row * N + bn + cb;
#pragma unroll
            for (int c = 0; c < 32; c++)
                cd[c] = __uint_as_float(rr[c]);
        }
        TCGEN05_FENCE_BEFORE();
    }
    __syncthreads();
    if (wid == 0) TCGEN05_DEALLOC(tmem, 128);

#else  // ---------------- SIMT fallback (baseline compute_103 pass) ---------
    float* As = (float*)dsm;
    float* Bs = As + 16 * 132;

    int tr = (tid >> 4) * 8;
    int tc = (tid & 15) * 8;

    float acc[8][8] = {};

    for (int k0 = 0; k0 < K; k0 += 16) {
#pragma unroll
        for (int e = 0; e < 8; e++) {
            int idx = tid * 8 + e;
            int kk = idx >> 7, rr = idx & 127;
            As[kk * 132 + rr] = __bfloat162float(Ah[(size_t)rr * ldK + k0 + kk]) +
                                __bfloat162float(Al[(size_t)rr * ldK + k0 + kk]);
            Bs[kk * 132 + rr] = __bfloat162float(Bh[(size_t)rr * ldK + k0 + kk]) +
                                __bfloat162float(Bl[(size_t)rr * ldK + k0 + kk]);
        }
        __syncthreads();
#pragma unroll
        for (int k = 0; k < 16; k++) {
            float ra[8], rb[8];
#pragma unroll
            for (int i = 0; i < 8; i++) ra[i] = As[k * 132 + tr + i];
#pragma unroll
            for (int j = 0; j < 8; j++) rb[j] = Bs[k * 132 + tc + j];
#pragma unroll
            for (int i = 0; i < 8; i++)
#pragma unroll
                for (int j = 0; j < 8; j++) acc[i][j] += ra[i] * rb[j];
        }
        __syncthreads();
    }

#pragma unroll
    for (int i = 0; i < 8; i++)
#pragma unroll
        for (int j = 0; j < 8; j++)
            Cz[(size_t)(bm + tr + i) * N + bn + tc + j] = acc[i][j];
#endif
}

// ---------------------------------------------------------------------------
// Projection with fused FC2 reduce: sh = relu(p0 + p1 + fc2_b), then
// out[n, j] = dot(sh, p_w[j,:]) + p_b[j], j < 20.
// ---------------------------------------------------------------------------
__global__ void proj_kernel(const float* __restrict__ part,
                            const float* __restrict__ fc2_b,
                            const float* __restrict__ p_w,
                            const float* __restrict__ p_b,
                            float* __restrict__ out, int NJ) {
    __shared__ float sh[1024];
    __shared__ float red[32][4];
    int n = blockIdx.x;
    int t = threadIdx.x;   // 128
    for (int i = t; i < 256; i += 128) {   // float4 over the 1024-row
        float4 a = ((const float4*)(part + (size_t)n * 1024))[i];
        float4 b = ((const float4*)(part + 1048576 + (size_t)n * 1024))[i];
        float4 bs = ((const float4*)fc2_b)[i];
        float4 o;
        o.x = fmaxf(a.x + b.x + bs.x, 0.0f);
        o.y = fmaxf(a.y + b.y + bs.y, 0.0f);
        o.z = fmaxf(a.z + b.z + bs.z, 0.0f);
        o.w = fmaxf(a.w + b.w + bs.w, 0.0f);
        ((float4*)sh)[i] = o;
    }
    __syncthreads();
    int j = t >> 2, ck = t & 3;
    if (j < NJ) {
        const float* wrow = p_w + (size_t)j * 1024 + ck * 256;
        const float* sv = sh + ck * 256;
        float s = 0.0f;
#pragma unroll 8
        for (int k = 0; k < 256; k++) s += sv[k] * wrow[k];
        red[j][ck] = s;
    }
    __syncthreads();
    if (t < NJ)
        out[(size_t)n * NJ + t] = red[t][0] + red[t][1] + red[t][2] + red[t][3] + p_b[t];
}

// ---------------------------------------------------------------------------
extern "C" void kernel_launch(void* const* d_in, const int* in_sizes, int n_in,
                              void* d_out, int out_size) {
    const float* fm0   = (const float*)d_in[0];
    const float* fm1   = (const float*)d_in[1];
    const float* fm2   = (const float*)d_in[2];
    const float* fm3   = (const float*)d_in[3];
    const float* rois  = (const float*)d_in[4];
    const float* fc1_w = (const float*)d_in[5];
    const float* fc1_b = (const float*)d_in[6];
    const float* fc2_w = (const float*)d_in[7];
    const float* fc2_b = (const float*)d_in[8];
    const float* p_w   = (const float*)d_in[9];
    const float* p_b   = (const float*)d_in[10];
    float* out = (float*)d_out;

    int nrois = in_sizes[4] / 5;   // 1024
    int nj = out_size / nrois;     // 20

    static cudaStream_t s2 = nullptr;
    static cudaEvent_t evF = nullptr, evJ1 = nullptr, evJ2 = nullptr;
    if (!s2) {
        cudaStreamCreateWithFlags(&s2, cudaStreamNonBlocking);
        cudaEventCreateWithFlags(&evF, cudaEventDisableTiming);
        cudaEventCreateWithFlags(&evJ1, cudaEventDisableTiming);
        cudaEventCreateWithFlags(&evJ2, cudaEventDisableTiming);
    }

    __nv_bfloat16 *w1h, *w1l, *w2h, *w2l, *p5h, *p5l, *f1h, *f1l;
    float* partp;
    cudaGetSymbolAddress((void**)&w1h, g_w1_hi);
    cudaGetSymbolAddress((void**)&w1l, g_w1_lo);
    cudaGetSymbolAddress((void**)&w2h, g_w2_hi);
    cudaGetSymbolAddress((void**)&w2l, g_w2_lo);
    cudaGetSymbolAddress((void**)&p5h, g_p5_hi);
    cudaGetSymbolAddress((void**)&p5l, g_p5_lo);
    cudaGetSymbolAddress((void**)&f1h, g_fc1_hi);
    cudaGetSymbolAddress((void**)&f1l, g_fc1_lo);
    cudaGetSymbolAddress((void**)&partp, g_part);

    // Fork: weight splits concurrent with transpose + ROI.
    // evJ1 gates the FC1 GEMM (needs w1 only); evJ2 gates the FC2 GEMM.
    cudaEventRecord(evF, 0);
    cudaStreamWaitEvent(s2, evF, 0);
    split_kernel<<<(12544 * 1024 / 4 + 255) / 256, 256, 0, s2>>>(fc1_w, w1h, w1l, 12544 * 1024 / 4);
    cudaEventRecord(evJ1, s2);
    split_kernel<<<(1024 * 1024 / 4 + 255) / 256, 256, 0, s2>>>(fc2_w, w2h, w2l, 1024 * 1024 / 4);
    cudaEventRecord(evJ2, s2);

    // Main: all-level NCHW fp32 -> NHWC fp16 in one launch, then ROIAlign.
    nchw2nhwc_all_kernel<<<dim3(319, 8, 2), 256>>>(fm0, fm1, fm2, fm3);

    cudaFuncSetAttribute(roi_align_kernel,
                         cudaFuncAttributeMaxDynamicSharedMemorySize, 50176);
    roi_align_kernel<<<nrois, 256, 50176>>>(rois);

    const int GEMM_SMEM = 1024 + 3 * 65536;  // 197632 (3-stage)
    cudaFuncSetAttribute(gemm_tc,
                         cudaFuncAttributeMaxDynamicSharedMemorySize, GEMM_SMEM);

    // FC1 split-K2: partials then reduce(+bias+relu+split to bf16 hi/lo).
    cudaStreamWaitEvent(0, evJ1, 0);
    gemm_tc<<<dim3(8, nrois / 128, 2), 256, GEMM_SMEM>>>(
        p5h, p5l, w1h, w1l, partp, 1024, 6272, 12544);
    reduce_split_kernel<<<1024, 256>>>(partp, fc1_b, f1h, f1l);

    // FC2 split-K2: partials; reduce fused into proj.
    cudaStreamWaitEvent(0, evJ2, 0);
    gemm_tc<<<dim3(8, nrois / 128, 2), 256, GEMM_SMEM>>>(
        f1h, f1l, w2h, w2l, partp, 1024, 512, 1024);

    // Projection (+ fused FC2 reduce)
    proj_kernel<<<nrois, 128>>>(partp, fc2_b, p_w, p_b, out, nj);
}

// round 15
// speedup vs baseline: 1.2106x; 1.0992x over previous
#include <cuda_runtime.h>
#include <cuda_bf16.h>
#include <cuda_fp16.h>
#include <cstdint>

// ---------------------------------------------------------------------------
// Shapes: B=2, C=256, Im 768x1280, strides {4,8,16,32}, N=1024 rois
// pool5 D = 12544 (K-major d = ch*49+bin), stored fp16.
// FC1: fp16 x fp16 tcgen05 (single product, fp32 accum), split-K2.
// FC2: bf16 hi/lo (3 products), split-K2, reduce fused into proj.
// ---------------------------------------------------------------------------

#define NCH 256

#if defined(__CUDA_ARCH__) && defined(__CUDA_ARCH_FEAT_SM103_ALL)
#define HAS_TCGEN05 1
#else
#define HAS_TCGEN05 0
#endif

__device__ __half g_nhwc[41779200];          // fp16 NHWC staging
__device__ __half g_p5[1024 * 12544];        // pool5, fp16
__device__ __half g_w1[1024 * 12544];        // fc1_w, fp16
__device__ __nv_bfloat16 g_fc1_hi[1024 * 1024];
__device__ __nv_bfloat16 g_fc1_lo[1024 * 1024];
__device__ __nv_bfloat16 g_w2_hi[1024 * 1024];
__device__ __nv_bfloat16 g_w2_lo[1024 * 1024];
__device__ float g_part[2 * 1024 * 1024];    // split-K2 partials

__constant__ size_t c_lvl_off[4] = {0, 31457280, 39321600, 41287680};

// ============================ PTX helpers ==================================
__device__ __forceinline__ uint32_t smem_u32(const void* p) {
    uint32_t a;
    asm("{ .reg .u64 t; cvta.to.shared.u64 t, %1; cvt.u32.u64 %0, t; }" : "=r"(a) : "l"(p));
    return a;
}
__device__ __forceinline__ uint32_t elect_one() {
    uint32_t p;
    asm volatile("{\n\t.reg .pred p;\n\telect.sync _|p, 0xFFFFFFFF;\n\tselp.b32 %0, 1, 0, p;\n\t}" : "=r"(p));
    return p;
}
#define MBARRIER_INIT(addr, cnt) \
    asm volatile("mbarrier.init.shared.b64 [%0], %1;" :: "r"(addr), "r"(cnt) : "memory")
#define MBARRIER_WAIT_PARITY(addr, par) do {                                          \
    uint32_t _m = (addr); uint32_t _p = (par); uint32_t _d;                           \
    asm volatile("{\n\t.reg .pred p;\n\t"                                             \
        "mbarrier.try_wait.parity.acquire.cta.shared::cta.b64 p, [%1], %2;\n\t"       \
        "selp.b32 %0, 1, 0, p;\n\t}" : "=r"(_d) : "r"(_m), "r"(_p) : "memory");       \
    if (!_d) {                                                                        \
        asm volatile("{\n\t.reg .pred P1;\n\t"                                        \
            "WL_%=:\n\t"                                                              \
            "mbarrier.try_wait.parity.acquire.cta.shared::cta.b64 P1, [%0], %1, 0x989680;\n\t" \
            "@P1 bra.uni WD_%=;\n\tbra.uni WL_%=;\n\tWD_%=:\n\t}"                     \
            :: "r"(_m), "r"(_p) : "memory");                                          \
    } } while (0)
#define FENCE_PROXY_ASYNC() asm volatile("fence.proxy.async.shared::cta;" ::: "memory")
#define CP_COMMIT() asm volatile("cp.async.commit_group;" ::: "memory")
#define CP_WAIT_1() asm volatile("cp.async.wait_group 1;" ::: "memory")

#if HAS_TCGEN05
#define TCGEN05_ALLOC(sa, n) \
    asm volatile("tcgen05.alloc.cta_group::1.sync.aligned.shared::cta.b32 [%0], %1;" :: "r"(sa), "r"(n) : "memory")
#define TCGEN05_DEALLOC(t, n) \
    asm volatile("tcgen05.dealloc.cta_group::1.sync.aligned.b32 %0, %1;" :: "r"(t), "r"(n))
#define TCGEN05_RELINQ() \
    asm volatile("tcgen05.relinquish_alloc_permit.cta_group::1.sync.aligned;")
#define TCGEN05_COMMIT(mb) \
    asm volatile("tcgen05.commit.cta_group::1.mbarrier::arrive::one.shared::cluster.b64 [%0];" :: "r"(mb) : "memory")
#define TCGEN05_FENCE_AFTER()  asm volatile("tcgen05.fence::after_thread_sync;" ::: "memory")
#define TCGEN05_FENCE_BEFORE() asm volatile("tcgen05.fence::before_thread_sync;" ::: "memory")
#define TCGEN05_WAIT_LD() asm volatile("tcgen05.wait::ld.sync.aligned;" ::: "memory")

#define TCGEN05_LD_X32(r, ta)                                                          \
    asm volatile("tcgen05.ld.sync.aligned.32x32b.x32.b32 "                             \
        "{%0, %1, %2, %3, %4, %5, %6, %7, %8, %9, %10, %11, %12, %13, %14, %15, "      \
        " %16, %17, %18, %19, %20, %21, %22, %23, %24, %25, %26, %27, %28, %29, %30, %31}, [%32];" \
        : "=r"((r)[0]), "=r"((r)[1]), "=r"((r)[2]), "=r"((r)[3]),                      \
          "=r"((r)[4]), "=r"((r)[5]), "=r"((r)[6]), "=r"((r)[7]),                      \
          "=r"((r)[8]), "=r"((r)[9]), "=r"((r)[10]), "=r"((r)[11]),                    \
          "=r"((r)[12]), "=r"((r)[13]), "=r"((r)[14]), "=r"((r)[15]),                  \
          "=r"((r)[16]), "=r"((r)[17]), "=r"((r)[18]), "=r"((r)[19]),                  \
          "=r"((r)[20]), "=r"((r)[21]), "=r"((r)[22]), "=r"((r)[23]),                  \
          "=r"((r)[24]), "=r"((r)[25]), "=r"((r)[26]), "=r"((r)[27]),                  \
          "=r"((r)[28]), "=r"((r)[29]), "=r"((r)[30]), "=r"((r)[31])                   \
        : "r"(ta))

__device__ __forceinline__ void mma_f16_ss(uint32_t d, uint64_t a, uint64_t b,
                                           uint32_t idesc, bool en) {
    uint32_t e = en ? 1u : 0u;
    asm volatile(
        "{\n\t.reg .pred p;\n\tsetp.ne.u32 p, %4, 0;\n\t"
        "tcgen05.mma.cta_group::1.kind::f16 [%0], %1, %2, %3, {%5, %5, %5, %5}, p;\n\t}"
        :: "r"(d), "l"(a), "l"(b), "r"(idesc), "r"(e), "r"(0u) : "memory");
}
#endif  // HAS_TCGEN05

// SW128 K-major descriptor: layout=2, version=1, SBO=64, LBO=1
static constexpr uint64_t DESC_BASE_SW128 =
    (uint64_t(2) << 61) | (uint64_t(1) << 46) | (uint64_t(64) << 32) | (uint64_t(1) << 16);
#define MAKE_DESC(a) (DESC_BASE_SW128 | ((uint64_t)((a) >> 4) & 0x3FFF))

// idesc kind::f16, F32 accum, M=128, N=128. BF16 variant sets a/b type = 1.
static constexpr uint32_t IDESC_BF16 =
    (1u << 4) | (1u << 7) | (1u << 10) | ((128u / 8u) << 17) | ((128u / 16u) << 24);
static constexpr uint32_t IDESC_FP16 =
    (1u << 4) | ((128u / 8u) << 17) | ((128u / 16u) << 24);

__device__ __forceinline__ void pack_hi_lo(float v0, float v1, uint32_t& h, uint32_t& l) {
    asm("cvt.rn.bf16x2.f32 %0, %1, %2;" : "=r"(h) : "f"(v1), "f"(v0));
    float l0 = v0 - __uint_as_float(h << 16);
    float l1 = v1 - __uint_as_float(h & 0xffff0000u);
    asm("cvt.rn.bf16x2.f32 %0, %1, %2;" : "=r"(l) : "f"(l1), "f"(l0));
}

// ---------------------------------------------------------------------------
// All-level NCHW fp32 -> NHWC fp16 transpose in ONE launch.
// ---------------------------------------------------------------------------
__global__ void nchw2nhwc_all_kernel(const float* __restrict__ fm0,
                                     const float* __restrict__ fm1,
                                     const float* __restrict__ fm2,
                                     const float* __restrict__ fm3) {
    __shared__ float tile[8][32][33];
    int bx = blockIdx.x;
    int lvl, bl;
    if      (bx < 240) { lvl = 0; bl = bx; }
    else if (bx < 300) { lvl = 1; bl = bx - 240; }
    else if (bx < 315) { lvl = 2; bl = bx - 300; }
    else               { lvl = 3; bl = bx - 315; }
    int HW = 61440 >> (2 * lvl);
    const float* in = (lvl == 0) ? fm0 : (lvl == 1) ? fm1 : (lvl == 2) ? fm2 : fm3;
    size_t off = c_lvl_off[lvl];

    int b = blockIdx.z;
    int c0 = blockIdx.y * 32;
    int t = threadIdx.x;
    int cr  = t >> 3;
    int f4  = t & 7;

    int hwbase = bl * 256;
    int nrep = (HW - hwbase + 31) >> 5;
    if (nrep > 8) nrep = 8;

    float4 v[8];
#pragma unroll
    for (int rep = 0; rep < 8; rep++)
        if (rep < nrep)
            v[rep] = *((const float4*)(in + ((size_t)b * NCH + c0 + cr) * HW + hwbase + rep * 32) + f4);

#pragma unroll
    for (int rep = 0; rep < 8; rep++)
        if (rep < nrep) {
            tile[rep][f4 * 4 + 0][cr] = v[rep].x;
            tile[rep][f4 * 4 + 1][cr] = v[rep].y;
            tile[rep][f4 * 4 + 2][cr] = v[rep].z;
            tile[rep][f4 * 4 + 3][cr] = v[rep].w;
        }
    __syncthreads();

#pragma unroll
    for (int rep = 0; rep < 8; rep++)
        if (rep < nrep) {
            half2 a = __floats2half2_rn(tile[rep][cr][f4 * 4 + 0], tile[rep][cr][f4 * 4 + 1]);
            half2 c = __floats2half2_rn(tile[rep][cr][f4 * 4 + 2], tile[rep][cr][f4 * 4 + 3]);
            uint2 o;
            o.x = *(uint32_t*)&a;
            o.y = *(uint32_t*)&c;
            *(uint2*)(g_nhwc + off + ((size_t)b * HW + hwbase + rep * 32 + cr) * NCH + c0 + f4 * 4) = o;
        }
}

// ---------------------------------------------------------------------------
// ROIAlign from fp16 NHWC: 32 channel-octets x 8 bin-groups, fp32 math,
// smem staging for coalesced K-major (ch*49+bin) fp16 output.
// ---------------------------------------------------------------------------
__device__ __forceinline__ void acc8(float* acc, uint4 v, float w) {
    half2* h = (half2*)&v;
#pragma unroll
    for (int e = 0; e < 4; e++) {
        float2 f = __half22float2(h[e]);
        acc[2 * e]     += w * f.x;
        acc[2 * e + 1] += w * f.y;
    }
}

__global__ void roi_align_kernel(const float* __restrict__ rois) {
    extern __shared__ float shbuf[];  // 12544 floats, [channel*49 + bin]
    __shared__ int   s_ix0[14], s_ix1[14], s_iy0[14], s_iy1[14];
    __shared__ float s_wx0[14], s_wx1[14], s_wy0[14], s_wy1[14];

    int n = blockIdx.x;
    int tid = threadIdx.x;
    int c8  = tid & 31;
    int grp = tid >> 5;

    const float* r = rois + (size_t)n * 5;
    int   b  = (int)r[0];
    float x1 = r[1], y1 = r[2], x2 = r[3], y2 = r[4];

    float w = x2 - x1, h = y2 - y1;
    float kf = floorf(4.0f + log2f(sqrtf(fmaxf(w * h, 1e-6f)) / 224.0f));
    kf = fminf(fmaxf(kf, 2.0f), 5.0f);
    int lvl = (int)kf - 2;

    float stride = (float)(4 << lvl);
    int H = 768 >> (lvl + 2);
    int W = 1280 >> (lvl + 2);
    const uint4* base4 = (const uint4*)(g_nhwc + c_lvl_off[lvl] + (size_t)b * H * W * NCH);

    if (tid < 28) {
        bool isx = tid < 14;
        int  s   = isx ? tid : tid - 14;
        float lo = isx ? x1 : y1;
        float hi = isx ? x2 : y2;
        int size = isx ? W : H;
        float a = lo / stride - 0.5f;
        float bb = hi / stride - 0.5f;
        float coord = a + (bb - a) * (((float)s + 0.5f) / 14.0f);
        float valid = (coord > -1.0f && coord < (float)size) ? 1.0f : 0.0f;
        float cc = fminf(fmaxf(coord, 0.0f), (float)(size - 1));
        int i0 = (int)floorf(cc);
        int i1 = min(i0 + 1, size - 1);
        float frac = cc - (float)i0;
        if (isx) { s_ix0[s] = i0; s_ix1[s] = i1; s_wx0[s] = (1.0f - frac) * valid; s_wx1[s] = frac * valid; }
        else     { s_iy0[s] = i0; s_iy1[s] = i1; s_wy0[s] = (1.0f - frac) * valid; s_wy1[s] = frac * valid; }
    }
    __syncthreads();

    for (int bin = grp; bin < 49; bin += 8) {
        int by = bin / 7, bx = bin - by * 7;
        float acc[8] = {};
#pragma unroll
        for (int i = 0; i < 2; i++) {
            int sy = by * 2 + i;
            float wy0 = s_wy0[sy], wy1 = s_wy1[sy];
            int row0 = s_iy0[sy] * W;
            int row1 = s_iy1[sy] * W;
#pragma unroll
            for (int j = 0; j < 2; j++) {
                int sx = bx * 2 + j;
                float wx0 = s_wx0[sx], wx1 = s_wx1[sx];
                int xa = s_ix0[sx], xb = s_ix1[sx];
                uint4 v00 = __ldg(base4 + (size_t)(row0 + xa) * 32 + c8);
                uint4 v01 = __ldg(base4 + (size_t)(row0 + xb) * 32 + c8);
                uint4 v10 = __ldg(base4 + (size_t)(row1 + xa) * 32 + c8);
                uint4 v11 = __ldg(base4 + (size_t)(row1 + xb) * 32 + c8);
                acc8(acc, v00, wy0 * wx0);
                acc8(acc, v01, wy0 * wx1);
                acc8(acc, v10, wy1 * wx0);
                acc8(acc, v11, wy1 * wx1);
            }
        }
        int ch = c8 * 8;
#pragma unroll
        for (int e = 0; e < 8; e++)
            shbuf[(ch + e) * 49 + bin] = acc[e] * 0.25f;
    }
    __syncthreads();

    uint32_t* hd = (uint32_t*)(g_p5 + (size_t)n * 12544);
    for (int i = tid; i < 6272; i += 256) {
        half2 p = __floats2half2_rn(shbuf[2 * i], shbuf[2 * i + 1]);
        hd[i] = *(uint32_t*)&p;
    }
}

// ---------------------------------------------------------------------------
// fc1_w: fp32 -> fp16 convert (single array)
// ---------------------------------------------------------------------------
__global__ void convert_h_kernel(const float* __restrict__ in,
                                 __half* __restrict__ outh, int n4) {
    int i = blockIdx.x * blockDim.x + threadIdx.x;
    if (i >= n4) return;
    float4 v = ((const float4*)in)[i];
    half2 a = __floats2half2_rn(v.x, v.y);
    half2 b = __floats2half2_rn(v.z, v.w);
    uint2 o;
    o.x = *(uint32_t*)&a;
    o.y = *(uint32_t*)&b;
    ((uint2*)outh)[i] = o;
}

// ---------------------------------------------------------------------------
// fc2_w: fp32 -> bf16 hi/lo split
// ---------------------------------------------------------------------------
__global__ void split_kernel(const float* __restrict__ in,
                             __nv_bfloat16* __restrict__ hi,
                             __nv_bfloat16* __restrict__ lo, int n4) {
    int i = blockIdx.x * blockDim.x + threadIdx.x;
    if (i >= n4) return;
    float4 v = ((const float4*)in)[i];
    uint32_t h0, h1, l0, l1;
    pack_hi_lo(v.x, v.y, h0, l0);
    pack_hi_lo(v.z, v.w, h1, l1);
    ((uint2*)hi)[i] = make_uint2(h0, h1);
    ((uint2*)lo)[i] = make_uint2(l0, l1);
}

// ---------------------------------------------------------------------------
// FC1 reduce: relu(p0 + p1 + bias) -> bf16 hi/lo (for FC2 inputs).
// ---------------------------------------------------------------------------
__global__ void reduce_split_kernel(const float* __restrict__ part,
                                    const float* __restrict__ bias,
                                    __nv_bfloat16* __restrict__ hi,
                                    __nv_bfloat16* __restrict__ lo) {
    int i = blockIdx.x * 256 + threadIdx.x;
    float4 a = ((const float4*)part)[i];
    float4 b = ((const float4*)(part + 1048576))[i];
    float4 bs = ((const float4*)bias)[i & 255];
    float v0 = fmaxf(a.x + b.x + bs.x, 0.0f);
    float v1 = fmaxf(a.y + b.y + bs.y, 0.0f);
    float v2 = fmaxf(a.z + b.z + bs.z, 0.0f);
    float v3 = fmaxf(a.w + b.w + bs.w, 0.0f);
    uint32_t h0, h1, l0, l1;
    pack_hi_lo(v0, v1, h0, l0);
    pack_hi_lo(v2, v3, h1, l1);
    ((uint2*)hi)[i] = make_uint2(h0, h1);
    ((uint2*)lo)[i] = make_uint2(l0, l1);
}

// ---------------------------------------------------------------------------
// GEMM template. PROD = 1: fp16 single product (Al/Bl unused).
//                PROD = 3: bf16 hi/lo, D = Ah*Bh + Ah*Bl + Al*Bh.
// 128x128 tile, BK=64, 3-stage cp.async pipeline with lagged MMA wait.
// blockIdx.z = split-K slice. Raw fp32 partial out.
// ---------------------------------------------------------------------------
__device__ __forceinline__ void load_tile16(uint32_t s_tile, const void* g,
                                            int ldK, int tid) {
#pragma unroll
    for (int q = 0; q < 4; q++) {
        int gid = tid + q * 256;
        int row = gid >> 3, c16 = gid & 7;
        uint32_t dst = s_tile + row * 128 + ((c16 ^ (row & 7)) << 4);
        const char* src = (const char*)g + (size_t)row * ldK * 2 + (c16 << 4);
        asm volatile("cp.async.cg.shared.global [%0], [%1], 16;" :: "r"(dst), "l"(src) : "memory");
    }
}

template <int PROD>
__global__ __launch_bounds__(256, 1) void gemm_tc(
    const uint16_t* __restrict__ Ah, const uint16_t* __restrict__ Al,
    const uint16_t* __restrict__ Bh, const uint16_t* __restrict__ Bl,
    float* __restrict__ Cf,
    int N, int K, int ldK) {
    extern __shared__ char dsm[];
    int tid = threadIdx.x;
    int bm = blockIdx.y * 128, bn = blockIdx.x * 128;
    int z = blockIdx.z;
    size_t koff = (size_t)z * K;

    const uint16_t* Ahp = Ah + (size_t)bm * ldK + koff;
    const uint16_t* Alp = (PROD == 3) ? Al + (size_t)bm * ldK + koff : nullptr;
    const uint16_t* Bhp = Bh + (size_t)bn * ldK + koff;
    const uint16_t* Blp = (PROD == 3) ? Bl + (size_t)bn * ldK + koff : nullptr;
    float* Cz = Cf + (size_t)z * (size_t)(gridDim.y * 128) * N;

    const uint32_t STG = (PROD == 3) ? 65536u : 32768u;
    const uint32_t OFF_B = (PROD == 3) ? 32768u : 16384u;
    const uint32_t idesc = (PROD == 3) ? IDESC_BF16 : IDESC_FP16;

#if HAS_TCGEN05
    __shared__ uint32_t s_tmem;
    __shared__ uint64_t s_mbar[3];

    uint32_t sbase = (smem_u32(dsm) + 1023u) & ~1023u;
    int wid = tid >> 5, lid = tid & 31;

    uint32_t mb[3] = { smem_u32(&s_mbar[0]), smem_u32(&s_mbar[1]), smem_u32(&s_mbar[2]) };

    if (wid == 0) TCGEN05_ALLOC(smem_u32(&s_tmem), 128);
    if (tid == 0) { MBARRIER_INIT(mb[0], 1); MBARRIER_INIT(mb[1], 1); MBARRIER_INIT(mb[2], 1); }
    __syncthreads();
    uint32_t tmem = s_tmem;
    if (wid == 0) TCGEN05_RELINQ();

    const int nblk = K >> 6;

#pragma unroll
    for (int p = 0; p < 2; p++) {
        uint32_t st = sbase + (uint32_t)p * STG;
        load_tile16(st,         Ahp + p * 64, ldK, tid);
        load_tile16(st + OFF_B, Bhp + p * 64, ldK, tid);
        if (PROD == 3) {
            load_tile16(st + 16384u, Alp + p * 64, ldK, tid);
            load_tile16(st + 49152u, Blp + p * 64, ldK, tid);
        }
        CP_COMMIT();
    }

    int ph[3] = {0, 0, 0};
    int s = 0, sp = 2;
    for (int i = 0; i < nblk; i++) {
        CP_WAIT_1();
        __syncthreads();
        if (tid < 32) {
            if (elect_one()) {
                FENCE_PROXY_ASYNC();
                uint32_t st = sbase + (uint32_t)s * STG;
                uint64_t dah = MAKE_DESC(st);
                uint64_t dbh = MAKE_DESC(st + OFF_B);
                bool en = (i > 0);
                if (PROD == 3) {
                    uint64_t dal = MAKE_DESC(st + 16384u);
                    uint64_t dbl = MAKE_DESC(st + 49152u);
#pragma unroll
                    for (int k = 0; k < 4; k++) {
                        mma_f16_ss(tmem, dah + k * 2, dbh + k * 2, idesc, en); en = true;
                        mma_f16_ss(tmem, dah + k * 2, dbl + k * 2, idesc, true);
                        mma_f16_ss(tmem, dal + k * 2, dbh + k * 2, idesc, true);
                    }
                } else {
#pragma unroll
                    for (int k = 0; k < 4; k++) {
                        mma_f16_ss(tmem, dah + k * 2, dbh + k * 2, idesc, en); en = true;
                    }
                }
                TCGEN05_COMMIT(mb[s]);
            }
        }
        if (i >= 1) {
            MBARRIER_WAIT_PARITY(mb[sp], ph[sp]);
            ph[sp] ^= 1;
            if (i + 2 < nblk) {
                uint32_t st = sbase + (uint32_t)sp * STG;
                int j = i + 2;
                load_tile16(st,         Ahp + j * 64, ldK, tid);
                load_tile16(st + OFF_B, Bhp + j * 64, ldK, tid);
                if (PROD == 3) {
                    load_tile16(st + 16384u, Alp + j * 64, ldK, tid);
                    load_tile16(st + 49152u, Blp + j * 64, ldK, tid);
                }
            }
        } else if (nblk > 2) {
            uint32_t st = sbase + 2u * STG;
            load_tile16(st,         Ahp + 2 * 64, ldK, tid);
            load_tile16(st + OFF_B, Bhp + 2 * 64, ldK, tid);
            if (PROD == 3) {
                load_tile16(st + 16384u, Alp + 2 * 64, ldK, tid);
                load_tile16(st + 49152u, Blp + 2 * 64, ldK, tid);
            }
        }
        CP_COMMIT();
        sp = s;
        s = (s == 2) ? 0 : s + 1;
    }

    {
        int lastS = (nblk - 1) % 3;
        MBARRIER_WAIT_PARITY(mb[lastS], ph[lastS]);
    }
    TCGEN05_FENCE_AFTER();

    if (tid < 128) {
        int row = bm + wid * 32 + lid;
#pragma unroll
        for (int cb = 0; cb < 128; cb += 32) {
            uint32_t rr[32];
            TCGEN05_LD_X32(rr, tmem + cb);
            TCGEN05_WAIT_LD();
            float* cd = Cz + (size_t)row * N + bn + cb;
#pragma unroll
            for (int c = 0; c < 32; c++)
                cd[c] = __uint_as_float(rr[c]);
        }
        TCGEN05_FENCE_BEFORE();
    }
    __syncthreads();
    if (wid == 0) TCGEN05_DEALLOC(tmem, 128);

#else  // ---------------- SIMT fallback (baseline compute_103 pass) ---------
    float* As = (float*)dsm;
    float* Bs = As + 16 * 132;

    int tr = (tid >> 4) * 8;
    int tc = (tid & 15) * 8;

    float acc[8][8] = {};

    for (int k0 = 0; k0 < K; k0 += 16) {
#pragma unroll
        for (int e = 0; e < 8; e++) {
            int idx = tid * 8 + e;
            int kk = idx >> 7, rr = idx & 127;
            if (PROD == 3) {
                As[kk * 132 + rr] =
                    __bfloat162float(((const __nv_bfloat16*)Ahp)[(size_t)rr * ldK + k0 + kk]) +
                    __bfloat162float(((const __nv_bfloat16*)Alp)[(size_t)rr * ldK + k0 + kk]);
                Bs[kk * 132 + rr] =
                    __bfloat162float(((const __nv_bfloat16*)Bhp)[(size_t)rr * ldK + k0 + kk]) +
                    __bfloat162float(((const __nv_bfloat16*)Blp)[(size_t)rr * ldK + k0 + kk]);
            } else {
                As[kk * 132 + rr] = __half2float(((const __half*)Ahp)[(size_t)rr * ldK + k0 + kk]);
                Bs[kk * 132 + rr] = __half2float(((const __half*)Bhp)[(size_t)rr * ldK + k0 + kk]);
            }
        }
        __syncthreads();
#pragma unroll
        for (int k = 0; k < 16; k++) {
            float ra[8], rb[8];
#pragma unroll
            for (int i = 0; i < 8; i++) ra[i] = As[k * 132 + tr + i];
#pragma unroll
            for (int j = 0; j < 8; j++) rb[j] = Bs[k * 132 + tc + j];
#pragma unroll
            for (int i = 0; i < 8; i++)
#pragma unroll
                for (int j = 0; j < 8; j++) acc[i][j] += ra[i] * rb[j];
        }
        __syncthreads();
    }

#pragma unroll
    for (int i = 0; i < 8; i++)
#pragma unroll
        for (int j = 0; j < 8; j++)
            Cz[(size_t)(bm + tr + i) * N + bn + tc + j] = acc[i][j];
#endif
}

// ---------------------------------------------------------------------------
// Projection with fused FC2 reduce: sh = relu(p0 + p1 + fc2_b), then
// out[n, j] = dot(sh, p_w[j,:]) + p_b[j], j < 20.
// ---------------------------------------------------------------------------
__global__ void proj_kernel(const float* __restrict__ part,
                            const float* __restrict__ fc2_b,
                            const float* __restrict__ p_w,
                            const float* __restrict__ p_b,
                            float* __restrict__ out, int NJ) {
    __shared__ float sh[1024];
    __shared__ float red[32][4];
    int n = blockIdx.x;
    int t = threadIdx.x;   // 128
    for (int i = t; i < 256; i += 128) {
        float4 a = ((const float4*)(part + (size_t)n * 1024))[i];
        float4 b = ((const float4*)(part + 1048576 + (size_t)n * 1024))[i];
        float4 bs = ((const float4*)fc2_b)[i];
        float4 o;
        o.x = fmaxf(a.x + b.x + bs.x, 0.0f);
        o.y = fmaxf(a.y + b.y + bs.y, 0.0f);
        o.z = fmaxf(a.z + b.z + bs.z, 0.0f);
        o.w = fmaxf(a.w + b.w + bs.w, 0.0f);
        ((float4*)sh)[i] = o;
    }
    __syncthreads();
    int j = t >> 2, ck = t & 3;
    if (j < NJ) {
        const float* wrow = p_w + (size_t)j * 1024 + ck * 256;
        const float* sv = sh + ck * 256;
        float s = 0.0f;
#pragma unroll 8
        for (int k = 0; k < 256; k++) s += sv[k] * wrow[k];
        red[j][ck] = s;
    }
    __syncthreads();
    if (t < NJ)
        out[(size_t)n * NJ + t] = red[t][0] + red[t][1] + red[t][2] + red[t][3] + p_b[t];
}

// ---------------------------------------------------------------------------
extern "C" void kernel_launch(void* const* d_in, const int* in_sizes, int n_in,
                              void* d_out, int out_size) {
    const float* fm0   = (const float*)d_in[0];
    const float* fm1   = (const float*)d_in[1];
    const float* fm2   = (const float*)d_in[2];
    const float* fm3   = (const float*)d_in[3];
    const float* rois  = (const float*)d_in[4];
    const float* fc1_w = (const float*)d_in[5];
    const float* fc1_b = (const float*)d_in[6];
    const float* fc2_w = (const float*)d_in[7];
    const float* fc2_b = (const float*)d_in[8];
    const float* p_w   = (const float*)d_in[9];
    const float* p_b   = (const float*)d_in[10];
    float* out = (float*)d_out;

    int nrois = in_sizes[4] / 5;   // 1024
    int nj = out_size / nrois;     // 20

    static cudaStream_t s2 = nullptr;
    static cudaEvent_t evF = nullptr, evJ1 = nullptr, evJ2 = nullptr;
    if (!s2) {
        cudaStreamCreateWithFlags(&s2, cudaStreamNonBlocking);
        cudaEventCreateWithFlags(&evF, cudaEventDisableTiming);
        cudaEventCreateWithFlags(&evJ1, cudaEventDisableTiming);
        cudaEventCreateWithFlags(&evJ2, cudaEventDisableTiming);
    }

    __half *p5p, *w1p;
    __nv_bfloat16 *w2h, *w2l, *f1h, *f1l;
    float* partp;
    cudaGetSymbolAddress((void**)&p5p, g_p5);
    cudaGetSymbolAddress((void**)&w1p, g_w1);
    cudaGetSymbolAddress((void**)&w2h, g_w2_hi);
    cudaGetSymbolAddress((void**)&w2l, g_w2_lo);
    cudaGetSymbolAddress((void**)&f1h, g_fc1_hi);
    cudaGetSymbolAddress((void**)&f1l, g_fc1_lo);
    cudaGetSymbolAddress((void**)&partp, g_part);

    // Fork: weight conversions concurrent with transpose + ROI.
    cudaEventRecord(evF, 0);
    cudaStreamWaitEvent(s2, evF, 0);
    convert_h_kernel<<<(12544 * 1024 / 4 + 255) / 256, 256, 0, s2>>>(fc1_w, w1p, 12544 * 1024 / 4);
    cudaEventRecord(evJ1, s2);
    split_kernel<<<(1024 * 1024 / 4 + 255) / 256, 256, 0, s2>>>(fc2_w, w2h, w2l, 1024 * 1024 / 4);
    cudaEventRecord(evJ2, s2);

    // Main: all-level NCHW fp32 -> NHWC fp16, then ROIAlign -> pool5 fp16.
    nchw2nhwc_all_kernel<<<dim3(319, 8, 2), 256>>>(fm0, fm1, fm2, fm3);

    cudaFuncSetAttribute(roi_align_kernel,
                         cudaFuncAttributeMaxDynamicSharedMemorySize, 50176);
    roi_align_kernel<<<nrois, 256, 50176>>>(rois);

    const int GEMM_SMEM = 1024 + 3 * 65536;  // max of both modes
    cudaFuncSetAttribute(gemm_tc<1>,
                         cudaFuncAttributeMaxDynamicSharedMemorySize, GEMM_SMEM);
    cudaFuncSetAttribute(gemm_tc<3>,
                         cudaFuncAttributeMaxDynamicSharedMemorySize, GEMM_SMEM);

    // FC1 split-K2 (fp16 x fp16): partials then reduce(+bias+relu+split).
    cudaStreamWaitEvent(0, evJ1, 0);
    gemm_tc<1><<<dim3(8, nrois / 128, 2), 256, 1024 + 3 * 32768>>>(
        (const uint16_t*)p5p, nullptr, (const uint16_t*)w1p, nullptr,
        partp, 1024, 6272, 12544);
    reduce_split_kernel<<<1024, 256>>>(partp, fc1_b, f1h, f1l);

    // FC2 split-K2 (bf16 hi/lo): partials; reduce fused into proj.
    cudaStreamWaitEvent(0, evJ2, 0);
    gemm_tc<3><<<dim3(8, nrois / 128, 2), 256, GEMM_SMEM>>>(
        (const uint16_t*)f1h, (const uint16_t*)f1l,
        (const uint16_t*)w2h, (const uint16_t*)w2l,
        partp, 1024, 512, 1024);

    // Projection (+ fused FC2 reduce)
    proj_kernel<<<nrois, 128>>>(partp, fc2_b, p_w, p_b, out, nj);
}

// round 16
// speedup vs baseline: 1.2840x; 1.0606x over previous
#include <cuda_runtime.h>
#include <cuda_bf16.h>
#include <cuda_fp16.h>
#include <cstdint>

// ---------------------------------------------------------------------------
// Shapes: B=2, C=256, Im 768x1280, strides {4,8,16,32}, N=1024 rois
// pool5 D = 12544 (K-major d = ch*49+bin), fp16.
// FC1: fp16 x fp16 tcgen05 single product, split-K2, fp32 accum.
// FC2: fp16 x fp16 single product, split-K2; reduce fused into proj.
// ---------------------------------------------------------------------------

#define NCH 256

#if defined(__CUDA_ARCH__) && defined(__CUDA_ARCH_FEAT_SM103_ALL)
#define HAS_TCGEN05 1
#else
#define HAS_TCGEN05 0
#endif

__device__ __half g_nhwc[41779200];          // fp16 NHWC staging
__device__ __half g_p5[1024 * 12544];        // pool5, fp16
__device__ __half g_w1[1024 * 12544];        // fc1_w, fp16
__device__ __half g_fc1[1024 * 1024];        // fc1 activations, fp16
__device__ __half g_w2[1024 * 1024];         // fc2_w, fp16
__device__ float g_part[2 * 1024 * 1024];    // split-K2 partials

__constant__ size_t c_lvl_off[4] = {0, 31457280, 39321600, 41287680};

// ============================ PTX helpers ==================================
__device__ __forceinline__ uint32_t smem_u32(const void* p) {
    uint32_t a;
    asm("{ .reg .u64 t; cvta.to.shared.u64 t, %1; cvt.u32.u64 %0, t; }" : "=r"(a) : "l"(p));
    return a;
}
__device__ __forceinline__ uint32_t elect_one() {
    uint32_t p;
    asm volatile("{\n\t.reg .pred p;\n\telect.sync _|p, 0xFFFFFFFF;\n\tselp.b32 %0, 1, 0, p;\n\t}" : "=r"(p));
    return p;
}
#define MBARRIER_INIT(addr, cnt) \
    asm volatile("mbarrier.init.shared.b64 [%0], %1;" :: "r"(addr), "r"(cnt) : "memory")
#define MBARRIER_WAIT_PARITY(addr, par) do {                                          \
    uint32_t _m = (addr); uint32_t _p = (par); uint32_t _d;                           \
    asm volatile("{\n\t.reg .pred p;\n\t"                                             \
        "mbarrier.try_wait.parity.acquire.cta.shared::cta.b64 p, [%1], %2;\n\t"       \
        "selp.b32 %0, 1, 0, p;\n\t}" : "=r"(_d) : "r"(_m), "r"(_p) : "memory");       \
    if (!_d) {                                                                        \
        asm volatile("{\n\t.reg .pred P1;\n\t"                                        \
            "WL_%=:\n\t"                                                              \
            "mbarrier.try_wait.parity.acquire.cta.shared::cta.b64 P1, [%0], %1, 0x989680;\n\t" \
            "@P1 bra.uni WD_%=;\n\tbra.uni WL_%=;\n\tWD_%=:\n\t}"                     \
            :: "r"(_m), "r"(_p) : "memory");                                          \
    } } while (0)
#define FENCE_PROXY_ASYNC() asm volatile("fence.proxy.async.shared::cta;" ::: "memory")
#define CP_COMMIT() asm volatile("cp.async.commit_group;" ::: "memory")
#define CP_WAIT_1() asm volatile("cp.async.wait_group 1;" ::: "memory")

#if HAS_TCGEN05
#define TCGEN05_ALLOC(sa, n) \
    asm volatile("tcgen05.alloc.cta_group::1.sync.aligned.shared::cta.b32 [%0], %1;" :: "r"(sa), "r"(n) : "memory")
#define TCGEN05_DEALLOC(t, n) \
    asm volatile("tcgen05.dealloc.cta_group::1.sync.aligned.b32 %0, %1;" :: "r"(t), "r"(n))
#define TCGEN05_RELINQ() \
    asm volatile("tcgen05.relinquish_alloc_permit.cta_group::1.sync.aligned;")
#define TCGEN05_COMMIT(mb) \
    asm volatile("tcgen05.commit.cta_group::1.mbarrier::arrive::one.shared::cluster.b64 [%0];" :: "r"(mb) : "memory")
#define TCGEN05_FENCE_AFTER()  asm volatile("tcgen05.fence::after_thread_sync;" ::: "memory")
#define TCGEN05_FENCE_BEFORE() asm volatile("tcgen05.fence::before_thread_sync;" ::: "memory")
#define TCGEN05_WAIT_LD() asm volatile("tcgen05.wait::ld.sync.aligned;" ::: "memory")

#define TCGEN05_LD_X32(r, ta)                                                          \
    asm volatile("tcgen05.ld.sync.aligned.32x32b.x32.b32 "                             \
        "{%0, %1, %2, %3, %4, %5, %6, %7, %8, %9, %10, %11, %12, %13, %14, %15, "      \
        " %16, %17, %18, %19, %20, %21, %22, %23, %24, %25, %26, %27, %28, %29, %30, %31}, [%32];" \
        : "=r"((r)[0]), "=r"((r)[1]), "=r"((r)[2]), "=r"((r)[3]),                      \
          "=r"((r)[4]), "=r"((r)[5]), "=r"((r)[6]), "=r"((r)[7]),                      \
          "=r"((r)[8]), "=r"((r)[9]), "=r"((r)[10]), "=r"((r)[11]),                    \
          "=r"((r)[12]), "=r"((r)[13]), "=r"((r)[14]), "=r"((r)[15]),                  \
          "=r"((r)[16]), "=r"((r)[17]), "=r"((r)[18]), "=r"((r)[19]),                  \
          "=r"((r)[20]), "=r"((r)[21]), "=r"((r)[22]), "=r"((r)[23]),                  \
          "=r"((r)[24]), "=r"((r)[25]), "=r"((r)[26]), "=r"((r)[27]),                  \
          "=r"((r)[28]), "=r"((r)[29]), "=r"((r)[30]), "=r"((r)[31])                   \
        : "r"(ta))

__device__ __forceinline__ void mma_f16_ss(uint32_t d, uint64_t a, uint64_t b,
                                           uint32_t idesc, bool en) {
    uint32_t e = en ? 1u : 0u;
    asm volatile(
        "{\n\t.reg .pred p;\n\tsetp.ne.u32 p, %4, 0;\n\t"
        "tcgen05.mma.cta_group::1.kind::f16 [%0], %1, %2, %3, {%5, %5, %5, %5}, p;\n\t}"
        :: "r"(d), "l"(a), "l"(b), "r"(idesc), "r"(e), "r"(0u) : "memory");
}
#endif  // HAS_TCGEN05

// SW128 K-major descriptor: layout=2, version=1, SBO=64, LBO=1
static constexpr uint64_t DESC_BASE_SW128 =
    (uint64_t(2) << 61) | (uint64_t(1) << 46) | (uint64_t(64) << 32) | (uint64_t(1) << 16);
#define MAKE_DESC(a) (DESC_BASE_SW128 | ((uint64_t)((a) >> 4) & 0x3FFF))

// idesc kind::f16, F32 accum, fp16 a/b, M=128, N=128
static constexpr uint32_t IDESC_FP16 =
    (1u << 4) | ((128u / 8u) << 17) | ((128u / 16u) << 24);

// ---------------------------------------------------------------------------
// All-level NCHW fp32 -> NHWC fp16 transpose in ONE launch.
// ---------------------------------------------------------------------------
__global__ void nchw2nhwc_all_kernel(const float* __restrict__ fm0,
                                     const float* __restrict__ fm1,
                                     const float* __restrict__ fm2,
                                     const float* __restrict__ fm3) {
    __shared__ float tile[8][32][33];
    int bx = blockIdx.x;
    int lvl, bl;
    if      (bx < 240) { lvl = 0; bl = bx; }
    else if (bx < 300) { lvl = 1; bl = bx - 240; }
    else if (bx < 315) { lvl = 2; bl = bx - 300; }
    else               { lvl = 3; bl = bx - 315; }
    int HW = 61440 >> (2 * lvl);
    const float* in = (lvl == 0) ? fm0 : (lvl == 1) ? fm1 : (lvl == 2) ? fm2 : fm3;
    size_t off = c_lvl_off[lvl];

    int b = blockIdx.z;
    int c0 = blockIdx.y * 32;
    int t = threadIdx.x;
    int cr  = t >> 3;
    int f4  = t & 7;

    int hwbase = bl * 256;
    int nrep = (HW - hwbase + 31) >> 5;
    if (nrep > 8) nrep = 8;

    float4 v[8];
#pragma unroll
    for (int rep = 0; rep < 8; rep++)
        if (rep < nrep)
            v[rep] = *((const float4*)(in + ((size_t)b * NCH + c0 + cr) * HW + hwbase + rep * 32) + f4);

#pragma unroll
    for (int rep = 0; rep < 8; rep++)
        if (rep < nrep) {
            tile[rep][f4 * 4 + 0][cr] = v[rep].x;
            tile[rep][f4 * 4 + 1][cr] = v[rep].y;
            tile[rep][f4 * 4 + 2][cr] = v[rep].z;
            tile[rep][f4 * 4 + 3][cr] = v[rep].w;
        }
    __syncthreads();

#pragma unroll
    for (int rep = 0; rep < 8; rep++)
        if (rep < nrep) {
            half2 a = __floats2half2_rn(tile[rep][cr][f4 * 4 + 0], tile[rep][cr][f4 * 4 + 1]);
            half2 c = __floats2half2_rn(tile[rep][cr][f4 * 4 + 2], tile[rep][cr][f4 * 4 + 3]);
            uint2 o;
            o.x = *(uint32_t*)&a;
            o.y = *(uint32_t*)&c;
            *(uint2*)(g_nhwc + off + ((size_t)b * HW + hwbase + rep * 32 + cr) * NCH + c0 + f4 * 4) = o;
        }
}

// ---------------------------------------------------------------------------
// ROIAlign from fp16 NHWC: 32 channel-octets x 8 bin-groups, fp32 math,
// fp16 smem staging (25KB), straight uint32 copy-out to K-major pool5.
// ---------------------------------------------------------------------------
__device__ __forceinline__ void acc8(float* acc, uint4 v, float w) {
    half2* h = (half2*)&v;
#pragma unroll
    for (int e = 0; e < 4; e++) {
        float2 f = __half22float2(h[e]);
        acc[2 * e]     += w * f.x;
        acc[2 * e + 1] += w * f.y;
    }
}

__global__ void roi_align_kernel(const float* __restrict__ rois) {
    extern __shared__ __half shbuf[];  // 12544 halves (25088B), [ch*49 + bin]
    __shared__ int   s_ix0[14], s_ix1[14], s_iy0[14], s_iy1[14];
    __shared__ float s_wx0[14], s_wx1[14], s_wy0[14], s_wy1[14];

    int n = blockIdx.x;
    int tid = threadIdx.x;
    int c8  = tid & 31;
    int grp = tid >> 5;

    const float* r = rois + (size_t)n * 5;
    int   b  = (int)r[0];
    float x1 = r[1], y1 = r[2], x2 = r[3], y2 = r[4];

    float w = x2 - x1, h = y2 - y1;
    float kf = floorf(4.0f + log2f(sqrtf(fmaxf(w * h, 1e-6f)) / 224.0f));
    kf = fminf(fmaxf(kf, 2.0f), 5.0f);
    int lvl = (int)kf - 2;

    float stride = (float)(4 << lvl);
    int H = 768 >> (lvl + 2);
    int W = 1280 >> (lvl + 2);
    const uint4* base4 = (const uint4*)(g_nhwc + c_lvl_off[lvl] + (size_t)b * H * W * NCH);

    if (tid < 28) {
        bool isx = tid < 14;
        int  s   = isx ? tid : tid - 14;
        float lo = isx ? x1 : y1;
        float hi = isx ? x2 : y2;
        int size = isx ? W : H;
        float a = lo / stride - 0.5f;
        float bb = hi / stride - 0.5f;
        float coord = a + (bb - a) * (((float)s + 0.5f) / 14.0f);
        float valid = (coord > -1.0f && coord < (float)size) ? 1.0f : 0.0f;
        float cc = fminf(fmaxf(coord, 0.0f), (float)(size - 1));
        int i0 = (int)floorf(cc);
        int i1 = min(i0 + 1, size - 1);
        float frac = cc - (float)i0;
        if (isx) { s_ix0[s] = i0; s_ix1[s] = i1; s_wx0[s] = (1.0f - frac) * valid; s_wx1[s] = frac * valid; }
        else     { s_iy0[s] = i0; s_iy1[s] = i1; s_wy0[s] = (1.0f - frac) * valid; s_wy1[s] = frac * valid; }
    }
    __syncthreads();

    for (int bin = grp; bin < 49; bin += 8) {
        int by = bin / 7, bx = bin - by * 7;
        float acc[8] = {};
#pragma unroll
        for (int i = 0; i < 2; i++) {
            int sy = by * 2 + i;
            float wy0 = s_wy0[sy], wy1 = s_wy1[sy];
            int row0 = s_iy0[sy] * W;
            int row1 = s_iy1[sy] * W;
#pragma unroll
            for (int j = 0; j < 2; j++) {
                int sx = bx * 2 + j;
                float wx0 = s_wx0[sx], wx1 = s_wx1[sx];
                int xa = s_ix0[sx], xb = s_ix1[sx];
                uint4 v00 = __ldg(base4 + (size_t)(row0 + xa) * 32 + c8);
                uint4 v01 = __ldg(base4 + (size_t)(row0 + xb) * 32 + c8);
                uint4 v10 = __ldg(base4 + (size_t)(row1 + xa) * 32 + c8);
                uint4 v11 = __ldg(base4 + (size_t)(row1 + xb) * 32 + c8);
                acc8(acc, v00, wy0 * wx0);
                acc8(acc, v01, wy0 * wx1);
                acc8(acc, v10, wy1 * wx0);
                acc8(acc, v11, wy1 * wx1);
            }
        }
        int ch = c8 * 8;
#pragma unroll
        for (int e = 0; e < 8; e++)
            shbuf[(ch + e) * 49 + bin] = __float2half(acc[e] * 0.25f);
    }
    __syncthreads();

    uint32_t* hd = (uint32_t*)(g_p5 + (size_t)n * 12544);
    const uint32_t* sp = (const uint32_t*)shbuf;
    for (int i = tid; i < 6272; i += 256) hd[i] = sp[i];
}

// ---------------------------------------------------------------------------
// fp32 -> fp16 convert (both weight matrices)
// ---------------------------------------------------------------------------
__global__ void convert_h_kernel(const float* __restrict__ in,
                                 __half* __restrict__ outh, int n4) {
    int i = blockIdx.x * blockDim.x + threadIdx.x;
    if (i >= n4) return;
    float4 v = ((const float4*)in)[i];
    half2 a = __floats2half2_rn(v.x, v.y);
    half2 b = __floats2half2_rn(v.z, v.w);
    uint2 o;
    o.x = *(uint32_t*)&a;
    o.y = *(uint32_t*)&b;
    ((uint2*)outh)[i] = o;
}

// ---------------------------------------------------------------------------
// FC1 reduce: relu(p0 + p1 + bias) -> fp16.
// ---------------------------------------------------------------------------
__global__ void reduce_h_kernel(const float* __restrict__ part,
                                const float* __restrict__ bias,
                                __half* __restrict__ outh) {
    int i = blockIdx.x * 256 + threadIdx.x;   // float4 index, 262144 total
    float4 a = ((const float4*)part)[i];
    float4 b = ((const float4*)(part + 1048576))[i];
    float4 bs = ((const float4*)bias)[i & 255];
    half2 p0 = __floats2half2_rn(fmaxf(a.x + b.x + bs.x, 0.0f),
                                 fmaxf(a.y + b.y + bs.y, 0.0f));
    half2 p1 = __floats2half2_rn(fmaxf(a.z + b.z + bs.z, 0.0f),
                                 fmaxf(a.w + b.w + bs.w, 0.0f));
    uint2 o;
    o.x = *(uint32_t*)&p0;
    o.y = *(uint32_t*)&p1;
    ((uint2*)outh)[i] = o;
}

// ---------------------------------------------------------------------------
// GEMM: fp16 x fp16 single product, 128x128 tile, BK=64, 3-stage cp.async
// pipeline with lagged MMA wait. blockIdx.z = split-K slice. fp32 partial out.
// ---------------------------------------------------------------------------
__device__ __forceinline__ void load_tile16(uint32_t s_tile, const __half* g,
                                            int ldK, int tid) {
#pragma unroll
    for (int q = 0; q < 4; q++) {
        int gid = tid + q * 256;
        int row = gid >> 3, c16 = gid & 7;
        uint32_t dst = s_tile + row * 128 + ((c16 ^ (row & 7)) << 4);
        const char* src = (const char*)g + (size_t)row * ldK * 2 + (c16 << 4);
        asm volatile("cp.async.cg.shared.global [%0], [%1], 16;" :: "r"(dst), "l"(src) : "memory");
    }
}

__global__ __launch_bounds__(256, 1) void gemm_tc(
    const __half* __restrict__ A, const __half* __restrict__ B,
    float* __restrict__ Cf,
    int N, int K, int ldK) {
    extern __shared__ char dsm[];
    int tid = threadIdx.x;
    int bm = blockIdx.y * 128, bn = blockIdx.x * 128;
    int z = blockIdx.z;
    size_t koff = (size_t)z * K;

    const __half* Ap = A + (size_t)bm * ldK + koff;
    const __half* Bp = B + (size_t)bn * ldK + koff;
    float* Cz = Cf + (size_t)z * (size_t)(gridDim.y * 128) * N;

#if HAS_TCGEN05
    __shared__ uint32_t s_tmem;
    __shared__ uint64_t s_mbar[3];

    uint32_t sbase = (smem_u32(dsm) + 1023u) & ~1023u;
    int wid = tid >> 5, lid = tid & 31;

    uint32_t mb[3] = { smem_u32(&s_mbar[0]), smem_u32(&s_mbar[1]), smem_u32(&s_mbar[2]) };

    if (wid == 0) TCGEN05_ALLOC(smem_u32(&s_tmem), 128);
    if (tid == 0) { MBARRIER_INIT(mb[0], 1); MBARRIER_INIT(mb[1], 1); MBARRIER_INIT(mb[2], 1); }
    __syncthreads();
    uint32_t tmem = s_tmem;
    if (wid == 0) TCGEN05_RELINQ();

    const int nblk = K >> 6;
    const uint32_t STG = 32768u;

#pragma unroll
    for (int p = 0; p < 2; p++) {
        uint32_t st = sbase + (uint32_t)p * STG;
        load_tile16(st,          Ap + p * 64, ldK, tid);
        load_tile16(st + 16384u, Bp + p * 64, ldK, tid);
        CP_COMMIT();
    }

    int ph[3] = {0, 0, 0};
    int s = 0, sp = 2;
    for (int i = 0; i < nblk; i++) {
        CP_WAIT_1();
        __syncthreads();
        if (tid < 32) {
            if (elect_one()) {
                FENCE_PROXY_ASYNC();
                uint32_t st = sbase + (uint32_t)s * STG;
                uint64_t da = MAKE_DESC(st);
                uint64_t db = MAKE_DESC(st + 16384u);
                bool en = (i > 0);
#pragma unroll
                for (int k = 0; k < 4; k++) {
                    mma_f16_ss(tmem, da + k * 2, db + k * 2, IDESC_FP16, en); en = true;
                }
                TCGEN05_COMMIT(mb[s]);
            }
        }
        if (i >= 1) {
            MBARRIER_WAIT_PARITY(mb[sp], ph[sp]);
            ph[sp] ^= 1;
            if (i + 2 < nblk) {
                uint32_t st = sbase + (uint32_t)sp * STG;
                int j = i + 2;
                load_tile16(st,          Ap + j * 64, ldK, tid);
                load_tile16(st + 16384u, Bp + j * 64, ldK, tid);
            }
        } else if (nblk > 2) {
            uint32_t st = sbase + 2u * STG;
            load_tile16(st,          Ap + 2 * 64, ldK, tid);
            load_tile16(st + 16384u, Bp + 2 * 64, ldK, tid);
        }
        CP_COMMIT();
        sp = s;
        s = (s == 2) ? 0 : s + 1;
    }

    {
        int lastS = (nblk - 1) % 3;
        MBARRIER_WAIT_PARITY(mb[lastS], ph[lastS]);
    }
    TCGEN05_FENCE_AFTER();

    if (tid < 128) {
        int row = bm + wid * 32 + lid;
#pragma unroll
        for (int cb = 0; cb < 128; cb += 32) {
            uint32_t rr[32];
            TCGEN05_LD_X32(rr, tmem + cb);
            TCGEN05_WAIT_LD();
            float* cd = Cz + (size_t)row * N + bn + cb;
#pragma unroll
            for (int c = 0; c < 32; c++)
                cd[c] = __uint_as_float(rr[c]);
        }
        TCGEN05_FENCE_BEFORE();
    }
    __syncthreads();
    if (wid == 0) TCGEN05_DEALLOC(tmem, 128);

#else  // ---------------- SIMT fallback (baseline compute_103 pass) ---------
    float* As = (float*)dsm;
    float* Bs = As + 16 * 132;

    int tr = (tid >> 4) * 8;
    int tc = (tid & 15) * 8;

    float acc[8][8] = {};

    for (int k0 = 0; k0 < K; k0 += 16) {
#pragma unroll
        for (int e = 0; e < 8; e++) {
            int idx = tid * 8 + e;
            int kk = idx >> 7, rr = idx & 127;
            As[kk * 132 + rr] = __half2float(Ap[(size_t)rr * ldK + k0 + kk]);
            Bs[kk * 132 + rr] = __half2float(Bp[(size_t)rr * ldK + k0 + kk]);
        }
        __syncthreads();
#pragma unroll
        for (int k = 0; k < 16; k++) {
            float ra[8], rb[8];
#pragma unroll
            for (int i = 0; i < 8; i++) ra[i] = As[k * 132 + tr + i];
#pragma unroll
            for (int j = 0; j < 8; j++) rb[j] = Bs[k * 132 + tc + j];
#pragma unroll
            for (int i = 0; i < 8; i++)
#pragma unroll
                for (int j = 0; j < 8; j++) acc[i][j] += ra[i] * rb[j];
        }
        __syncthreads();
    }

#pragma unroll
    for (int i = 0; i < 8; i++)
#pragma unroll
        for (int j = 0; j < 8; j++)
            Cz[(size_t)(bm + tr + i) * N + bn + tc + j] = acc[i][j];
#endif
}

// ---------------------------------------------------------------------------
// Projection with fused FC2 reduce: sh = relu(p0 + p1 + fc2_b), then
// out[n, j] = dot(sh, p_w[j,:]) + p_b[j], j < 20.
// ---------------------------------------------------------------------------
__global__ void proj_kernel(const float* __restrict__ part,
                            const float* __restrict__ fc2_b,
                            const float* __restrict__ p_w,
                            const float* __restrict__ p_b,
                            float* __restrict__ out, int NJ) {
    __shared__ float sh[1024];
    __shared__ float red[32][4];
    int n = blockIdx.x;
    int t = threadIdx.x;   // 128
    for (int i = t; i < 256; i += 128) {
        float4 a = ((const float4*)(part + (size_t)n * 1024))[i];
        float4 b = ((const float4*)(part + 1048576 + (size_t)n * 1024))[i];
        float4 bs = ((const float4*)fc2_b)[i];
        float4 o;
        o.x = fmaxf(a.x + b.x + bs.x, 0.0f);
        o.y = fmaxf(a.y + b.y + bs.y, 0.0f);
        o.z = fmaxf(a.z + b.z + bs.z, 0.0f);
        o.w = fmaxf(a.w + b.w + bs.w, 0.0f);
        ((float4*)sh)[i] = o;
    }
    __syncthreads();
    int j = t >> 2, ck = t & 3;
    if (j < NJ) {
        const float* wrow = p_w + (size_t)j * 1024 + ck * 256;
        const float* sv = sh + ck * 256;
        float s = 0.0f;
#pragma unroll 8
        for (int k = 0; k < 256; k++) s += sv[k] * wrow[k];
        red[j][ck] = s;
    }
    __syncthreads();
    if (t < NJ)
        out[(size_t)n * NJ + t] = red[t][0] + red[t][1] + red[t][2] + red[t][3] + p_b[t];
}

// ---------------------------------------------------------------------------
extern "C" void kernel_launch(void* const* d_in, const int* in_sizes, int n_in,
                              void* d_out, int out_size) {
    const float* fm0   = (const float*)d_in[0];
    const float* fm1   = (const float*)d_in[1];
    const float* fm2   = (const float*)d_in[2];
    const float* fm3   = (const float*)d_in[3];
    const float* rois  = (const float*)d_in[4];
    const float* fc1_w = (const float*)d_in[5];
    const float* fc1_b = (const float*)d_in[6];
    const float* fc2_w = (const float*)d_in[7];
    const float* fc2_b = (const float*)d_in[8];
    const float* p_w   = (const float*)d_in[9];
    const float* p_b   = (const float*)d_in[10];
    float* out = (float*)d_out;

    int nrois = in_sizes[4] / 5;   // 1024
    int nj = out_size / nrois;     // 20

    static cudaStream_t s2 = nullptr;
    static cudaEvent_t evF = nullptr, evJ1 = nullptr, evJ2 = nullptr;
    if (!s2) {
        cudaStreamCreateWithFlags(&s2, cudaStreamNonBlocking);
        cudaEventCreateWithFlags(&evF, cudaEventDisableTiming);
        cudaEventCreateWithFlags(&evJ1, cudaEventDisableTiming);
        cudaEventCreateWithFlags(&evJ2, cudaEventDisableTiming);
    }

    __half *p5p, *w1p, *w2p, *f1p;
    float* partp;
    cudaGetSymbolAddress((void**)&p5p, g_p5);
    cudaGetSymbolAddress((void**)&w1p, g_w1);
    cudaGetSymbolAddress((void**)&w2p, g_w2);
    cudaGetSymbolAddress((void**)&f1p, g_fc1);
    cudaGetSymbolAddress((void**)&partp, g_part);

    // Fork: weight conversions concurrent with transpose + ROI.
    cudaEventRecord(evF, 0);
    cudaStreamWaitEvent(s2, evF, 0);
    convert_h_kernel<<<(12544 * 1024 / 4 + 255) / 256, 256, 0, s2>>>(fc1_w, w1p, 12544 * 1024 / 4);
    cudaEventRecord(evJ1, s2);
    convert_h_kernel<<<(1024 * 1024 / 4 + 255) / 256, 256, 0, s2>>>(fc2_w, w2p, 1024 * 1024 / 4);
    cudaEventRecord(evJ2, s2);

    // Main: all-level NCHW fp32 -> NHWC fp16, then ROIAlign -> pool5 fp16.
    nchw2nhwc_all_kernel<<<dim3(319, 8, 2), 256>>>(fm0, fm1, fm2, fm3);

    cudaFuncSetAttribute(roi_align_kernel,
                         cudaFuncAttributeMaxDynamicSharedMemorySize, 25088);
    roi_align_kernel<<<nrois, 256, 25088>>>(rois);

    const int GEMM_SMEM = 1024 + 3 * 32768;  // 99328 (3-stage, 32KB/stage)
    cudaFuncSetAttribute(gemm_tc,
                         cudaFuncAttributeMaxDynamicSharedMemorySize, GEMM_SMEM);

    // FC1 split-K2 (fp16): partials then reduce(+bias+relu) -> fp16.
    cudaStreamWaitEvent(0, evJ1, 0);
    gemm_tc<<<dim3(8, nrois / 128, 2), 256, GEMM_SMEM>>>(
        p5p, w1p, partp, 1024, 6272, 12544);
    reduce_h_kernel<<<1024, 256>>>(partp, fc1_b, f1p);

    // FC2 split-K2 (fp16): partials; reduce fused into proj.
    cudaStreamWaitEvent(0, evJ2, 0);
    gemm_tc<<<dim3(8, nrois / 128, 2), 256, GEMM_SMEM>>>(
        f1p, w2p, partp, 1024, 512, 1024);

    // Projection (+ fused FC2 reduce)
    proj_kernel<<<nrois, 128>>>(partp, fc2_b, p_w, p_b, out, nj);
}